// round 13
// baseline (speedup 1.0000x reference)
#include <cuda_runtime.h>
#include <cuda_fp16.h>
#include <math.h>
#include <stdint.h>

#define BATCH 8192
#define KDIM  1024
#define HDIM  1024
#define FH    4096

// Scratch: fp16 gate pre-activations + fp16 operand copies.
__device__ __half g_ig[(size_t)BATCH * FH];
__device__ __half g_hg[(size_t)BATCH * FH];
__device__ __half g_A [(size_t)BATCH * KDIM];
__device__ __half g_H [(size_t)BATCH * KDIM];
__device__ __half g_Wi[(size_t)FH * KDIM];
__device__ __half g_Wh[(size_t)FH * KDIM];

// ---------------------------------------------------------------------------
// fp32 -> fp16 (RN) conversion, all 4 tensors in one launch.
// ---------------------------------------------------------------------------
__global__ void __launch_bounds__(256)
cvt_fp16_kernel(const float* __restrict__ s0, const float* __restrict__ s1,
                const float* __restrict__ s2, const float* __restrict__ s3,
                __half* __restrict__ d0, __half* __restrict__ d1,
                __half* __restrict__ d2, __half* __restrict__ d3)
{
    const float* src; __half* dst; int n4;
    switch (blockIdx.y) {
        case 0: src = s0; dst = d0; n4 = (BATCH * KDIM) / 4; break;
        case 1: src = s1; dst = d1; n4 = (BATCH * KDIM) / 4; break;
        case 2: src = s2; dst = d2; n4 = (FH * KDIM) / 4; break;
        default: src = s3; dst = d3; n4 = (FH * KDIM) / 4; break;
    }
    int i = blockIdx.x * blockDim.x + threadIdx.x;
    int stride = gridDim.x * blockDim.x;
    for (; i < n4; i += stride) {
        float4 v = ((const float4*)src)[i];
        __half2 lo = __floats2half2_rn(v.x, v.y);
        __half2 hi = __floats2half2_rn(v.z, v.w);
        uint2 p;
        p.x = *(uint32_t*)&lo;
        p.y = *(uint32_t*)&hi;
        ((uint2*)dst)[i] = p;
    }
}

// ---------------------------------------------------------------------------
// GEMM: out[m,n] = sum_k A[m,k] * W[n,k]  via mma.sync m16n8k16.f16 (fp32 acc)
// CTA tile 128x256, K-chunk 64, 3 stages, 8 warps (2x4), warp tile 64x64.
// At the measured legacy tensor-pipe MAC floor: frozen.
// ---------------------------------------------------------------------------
#define BM 128
#define BN 256
#define KC 64
#define NCHUNK (KDIM / KC)                 // 16
#define ROWB  144
#define A_B   (BM * ROWB)
#define B_B   (BN * ROWB)
#define STAGE_BYTES (A_B + B_B)
#define SMEM_TOTAL (3 * STAGE_BYTES)
#define NTHREADS 256

__device__ __forceinline__ uint32_t smem_u32(const void* p) {
    uint32_t a;
    asm("{ .reg .u64 t; cvta.to.shared.u64 t, %1; cvt.u32.u64 %0, t; }" : "=r"(a) : "l"(p));
    return a;
}

__device__ __forceinline__ void cp16(uint32_t saddr, const void* g) {
    asm volatile("cp.async.cg.shared.global [%0], [%1], 16;" :: "r"(saddr), "l"(g));
}
#define CP_COMMIT() asm volatile("cp.async.commit_group;" ::: "memory")
#define CP_WAIT_1() asm volatile("cp.async.wait_group 1;" ::: "memory")

__device__ __forceinline__ void ldsm4(uint32_t& r0, uint32_t& r1, uint32_t& r2, uint32_t& r3,
                                      uint32_t addr) {
    asm volatile("ldmatrix.sync.aligned.m8n8.x4.shared.b16 {%0,%1,%2,%3}, [%4];"
                 : "=r"(r0), "=r"(r1), "=r"(r2), "=r"(r3) : "r"(addr));
}

__device__ __forceinline__ void mma_f16(float c[4], const uint32_t a[4], const uint32_t b[2]) {
    asm volatile(
        "mma.sync.aligned.m16n8k16.row.col.f32.f16.f16.f32 "
        "{%0,%1,%2,%3}, {%4,%5,%6,%7}, {%8,%9}, {%0,%1,%2,%3};"
        : "+f"(c[0]), "+f"(c[1]), "+f"(c[2]), "+f"(c[3])
        : "r"(a[0]), "r"(a[1]), "r"(a[2]), "r"(a[3]),
          "r"(b[0]), "r"(b[1]));
}

__global__ void __launch_bounds__(NTHREADS, 1)
gemm_f16_kernel(const __half* __restrict__ gA, const __half* __restrict__ gH,
                const __half* __restrict__ gWi, const __half* __restrict__ gWh)
{
    extern __shared__ char smem[];
    const uint32_t sbase = smem_u32(smem);

    const __half* A  = (blockIdx.z == 0) ? gA  : gH;
    const __half* W  = (blockIdx.z == 0) ? gWi : gWh;
    __half*      out = (blockIdx.z == 0) ? g_ig : g_hg;

    const int tid  = threadIdx.x;
    const int wid  = tid >> 5;
    const int lane = tid & 31;
    const int wm   = wid >> 2;
    const int wn   = wid & 3;
    const int m0   = blockIdx.y * BM;
    const int n0   = blockIdx.x * BN;

    const int ldrow = tid >> 3;
    const int ldc   = tid & 7;

    auto load_stage = [&](int st, int c) {
        const uint32_t sA = sbase + st * STAGE_BYTES;
        const uint32_t sB = sA + A_B;
        const int kt = c * KC;
        #pragma unroll
        for (int i = 0; i < 4; i++) {
            int row = ldrow + i * 32;
            cp16(sA + row * ROWB + ldc * 16,
                 &A[(size_t)(m0 + row) * KDIM + kt + ldc * 8]);
        }
        #pragma unroll
        for (int i = 0; i < 8; i++) {
            int row = ldrow + i * 32;
            cp16(sB + row * ROWB + ldc * 16,
                 &W[(size_t)(n0 + row) * KDIM + kt + ldc * 8]);
        }
    };

    const int lrow = lane & 15;
    const int lkof = (lane >> 4) * 16;
    uint32_t offA[4], offB[4];
    #pragma unroll
    for (int mt = 0; mt < 4; mt++)
        offA[mt] = (wm * 64 + mt * 16 + lrow) * ROWB + lkof;
    #pragma unroll
    for (int p = 0; p < 4; p++)
        offB[p] = (uint32_t)A_B + (wn * 64 + p * 16 + lrow) * ROWB + lkof;

    float acc[4][8][4];
    #pragma unroll
    for (int mt = 0; mt < 4; mt++)
        #pragma unroll
        for (int nt = 0; nt < 8; nt++)
            #pragma unroll
            for (int r = 0; r < 4; r++)
                acc[mt][nt][r] = 0.f;

    load_stage(0, 0); CP_COMMIT();
    load_stage(1, 1); CP_COMMIT();

    int st = 0;
    for (int c = 0; c < NCHUNK; c++) {
        CP_WAIT_1();
        __syncthreads();

        int st2 = st + 2; if (st2 >= 3) st2 -= 3;
        if (c + 2 < NCHUNK) load_stage(st2, c + 2);
        CP_COMMIT();

        const uint32_t sb = sbase + st * STAGE_BYTES;

        #pragma unroll
        for (int ks = 0; ks < 4; ks++) {
            const uint32_t kb = ks * 32;

            uint32_t af[4][4];
            #pragma unroll
            for (int mt = 0; mt < 4; mt++)
                ldsm4(af[mt][0], af[mt][1], af[mt][2], af[mt][3], sb + offA[mt] + kb);
            uint32_t bf[8][2];
            #pragma unroll
            for (int p = 0; p < 4; p++)
                ldsm4(bf[2*p][0], bf[2*p+1][0], bf[2*p][1], bf[2*p+1][1],
                      sb + offB[p] + kb);
            #pragma unroll
            for (int mt = 0; mt < 4; mt++)
                #pragma unroll
                for (int nt = 0; nt < 8; nt++)
                    mma_f16(acc[mt][nt], af[mt], bf[nt]);
        }

        if (++st >= 3) st -= 3;
    }

    #pragma unroll
    for (int mt = 0; mt < 4; mt++) {
        int row0 = m0 + wm * 64 + mt * 16 + (lane >> 2);
        #pragma unroll
        for (int nt = 0; nt < 8; nt++) {
            int col0 = n0 + wn * 64 + nt * 8 + 2 * (lane & 3);
            __half2 v0 = __floats2half2_rn(acc[mt][nt][0], acc[mt][nt][1]);
            __half2 v1 = __floats2half2_rn(acc[mt][nt][2], acc[mt][nt][3]);
            *(__half2*)&out[(size_t)row0 * FH + col0]       = v0;
            *(__half2*)&out[(size_t)(row0 + 8) * FH + col0] = v1;
        }
    }
}

// ---------------------------------------------------------------------------
// Fused LayerNorm + LSTM gates + cell LayerNorm.
// PERSISTENT: 512 CTAs x 16 rows each, next-row gate/cx loads issued before
// the current row's block reductions (latency hidden behind barriers/stores).
// ---------------------------------------------------------------------------
#define FUSE_CTAS 512
#define ROWS_PER_CTA (BATCH / FUSE_CTAS)   // 16

__device__ __forceinline__ float sigmoidf_(float x) {
    return 1.f / (1.f + expf(-x));
}

__device__ __forceinline__ float4 unpack4(uint2 u) {
    __half2 h0 = *(__half2*)&u.x;
    __half2 h1 = *(__half2*)&u.y;
    float2 f0 = __half22float2(h0);
    float2 f1 = __half22float2(h1);
    return make_float4(f0.x, f0.y, f1.x, f1.y);
}

__device__ __forceinline__ float4 block_sum4(float4 v, float4* sh) {
    #pragma unroll
    for (int o = 16; o > 0; o >>= 1) {
        v.x += __shfl_down_sync(0xffffffffu, v.x, o);
        v.y += __shfl_down_sync(0xffffffffu, v.y, o);
        v.z += __shfl_down_sync(0xffffffffu, v.z, o);
        v.w += __shfl_down_sync(0xffffffffu, v.w, o);
    }
    int lane = threadIdx.x & 31, w = threadIdx.x >> 5;
    if (lane == 0) sh[w] = v;
    __syncthreads();
    if (w == 0) {
        float4 t = (lane < 8) ? sh[lane] : make_float4(0.f, 0.f, 0.f, 0.f);
        #pragma unroll
        for (int o = 4; o > 0; o >>= 1) {
            t.x += __shfl_down_sync(0xffffffffu, t.x, o);
            t.y += __shfl_down_sync(0xffffffffu, t.y, o);
            t.z += __shfl_down_sync(0xffffffffu, t.z, o);
            t.w += __shfl_down_sync(0xffffffffu, t.w, o);
        }
        if (lane == 0) sh[0] = t;
    }
    __syncthreads();
    return sh[0];
}

__device__ __forceinline__ float2 block_sum2(float2 v, float2* sh) {
    #pragma unroll
    for (int o = 16; o > 0; o >>= 1) {
        v.x += __shfl_down_sync(0xffffffffu, v.x, o);
        v.y += __shfl_down_sync(0xffffffffu, v.y, o);
    }
    int lane = threadIdx.x & 31, w = threadIdx.x >> 5;
    if (lane == 0) sh[w] = v;
    __syncthreads();
    if (w == 0) {
        float2 t = (lane < 8) ? sh[lane] : make_float2(0.f, 0.f);
        #pragma unroll
        for (int o = 4; o > 0; o >>= 1) {
            t.x += __shfl_down_sync(0xffffffffu, t.x, o);
            t.y += __shfl_down_sync(0xffffffffu, t.y, o);
        }
        if (lane == 0) sh[0] = t;
    }
    __syncthreads();
    return sh[0];
}

__global__ void __launch_bounds__(256)
fuse_kernel(const float* __restrict__ cx,
            const float* __restrict__ ln_i_w, const float* __restrict__ ln_i_b,
            const float* __restrict__ ln_h_w, const float* __restrict__ ln_h_b,
            const float* __restrict__ ln_c_w, const float* __restrict__ ln_c_b,
            float* __restrict__ out)
{
    const int tid = threadIdx.x;
    const int b0  = blockIdx.x * ROWS_PER_CTA;

    __shared__ float4 red4[8];
    __shared__ float2 red_c[8];

    // current-row and next-row packed gate buffers + cx
    uint2 pa[4], pb[4], na[4], nb[4];
    float4 c4, nc4;

    {
        const uint2* ig2 = (const uint2*)(g_ig + (size_t)b0 * FH);
        const uint2* hg2 = (const uint2*)(g_hg + (size_t)b0 * FH);
        #pragma unroll
        for (int p = 0; p < 4; p++) {
            pa[p] = ig2[tid + p * 256];
            pb[p] = hg2[tid + p * 256];
        }
        c4 = ((const float4*)cx)[(size_t)b0 * 256 + tid];
    }

    #pragma unroll 1
    for (int r = 0; r < ROWS_PER_CTA; r++) {
        const int b = b0 + r;

        // stats for current row
        float4 s = make_float4(0.f, 0.f, 0.f, 0.f);
        #pragma unroll
        for (int p = 0; p < 4; p++) {
            float4 a = unpack4(pa[p]);
            float4 c = unpack4(pb[p]);
            s.x += a.x + a.y + a.z + a.w;
            s.y += a.x*a.x + a.y*a.y + a.z*a.z + a.w*a.w;
            s.z += c.x + c.y + c.z + c.w;
            s.w += c.x*c.x + c.y*c.y + c.z*c.z + c.w*c.w;
        }

        // prefetch next row (hidden behind the reductions below)
        if (r + 1 < ROWS_PER_CTA) {
            const uint2* ig2 = (const uint2*)(g_ig + (size_t)(b + 1) * FH);
            const uint2* hg2 = (const uint2*)(g_hg + (size_t)(b + 1) * FH);
            #pragma unroll
            for (int p = 0; p < 4; p++) {
                na[p] = ig2[tid + p * 256];
                nb[p] = hg2[tid + p * 256];
            }
            nc4 = ((const float4*)cx)[(size_t)(b + 1) * 256 + tid];
        }

        float4 rr = block_sum4(s, red4);

        const float inv_fh = 1.f / (float)FH;
        float mu_i = rr.x * inv_fh;
        float rs_i = rsqrtf(rr.y * inv_fh - mu_i * mu_i + 1e-5f);
        float mu_h = rr.z * inv_fh;
        float rs_h = rsqrtf(rr.w * inv_fh - mu_h * mu_h + 1e-5f);

        float4 g[4];
        #pragma unroll
        for (int p = 0; p < 4; p++) {
            int j = tid + p * 256;
            float4 wi = ((const float4*)ln_i_w)[j], bi = ((const float4*)ln_i_b)[j];
            float4 wh = ((const float4*)ln_h_w)[j], bh = ((const float4*)ln_h_b)[j];
            float4 a = unpack4(pa[p]);
            float4 c = unpack4(pb[p]);
            g[p].x = (a.x - mu_i) * rs_i * wi.x + bi.x + (c.x - mu_h) * rs_h * wh.x + bh.x;
            g[p].y = (a.y - mu_i) * rs_i * wi.y + bi.y + (c.y - mu_h) * rs_h * wh.y + bh.y;
            g[p].z = (a.z - mu_i) * rs_i * wi.z + bi.z + (c.z - mu_h) * rs_h * wh.z + bh.z;
            g[p].w = (a.w - mu_i) * rs_i * wi.w + bi.w + (c.w - mu_h) * rs_h * wh.w + bh.w;
        }

        float4 cv;
        cv.x = sigmoidf_(g[1].x) * c4.x + sigmoidf_(g[0].x) * tanhf(g[2].x);
        cv.y = sigmoidf_(g[1].y) * c4.y + sigmoidf_(g[0].y) * tanhf(g[2].y);
        cv.z = sigmoidf_(g[1].z) * c4.z + sigmoidf_(g[0].z) * tanhf(g[2].z);
        cv.w = sigmoidf_(g[1].w) * c4.w + sigmoidf_(g[0].w) * tanhf(g[2].w);

        float2 sc = make_float2(cv.x + cv.y + cv.z + cv.w,
                                cv.x*cv.x + cv.y*cv.y + cv.z*cv.z + cv.w*cv.w);
        float2 rc = block_sum2(sc, red_c);
        const float inv_h = 1.f / (float)HDIM;
        float mu_c = rc.x * inv_h;
        float rs_c = rsqrtf(rc.y * inv_h - mu_c * mu_c + 1e-5f);

        float4 wc = ((const float4*)ln_c_w)[tid], bc = ((const float4*)ln_c_b)[tid];
        float4 cy, hy;
        cy.x = (cv.x - mu_c) * rs_c * wc.x + bc.x;  hy.x = sigmoidf_(g[3].x) * tanhf(cy.x);
        cy.y = (cv.y - mu_c) * rs_c * wc.y + bc.y;  hy.y = sigmoidf_(g[3].y) * tanhf(cy.y);
        cy.z = (cv.z - mu_c) * rs_c * wc.z + bc.z;  hy.z = sigmoidf_(g[3].z) * tanhf(cy.z);
        cy.w = (cv.w - mu_c) * rs_c * wc.w + bc.w;  hy.w = sigmoidf_(g[3].w) * tanhf(cy.w);

        ((float4*)out)[(size_t)b * 256 + tid] = hy;
        ((float4*)out)[(size_t)BATCH * 256 + (size_t)b * 256 + tid] = cy;

        // rotate prefetch buffers
        #pragma unroll
        for (int p = 0; p < 4; p++) { pa[p] = na[p]; pb[p] = nb[p]; }
        c4 = nc4;
    }
}

// ---------------------------------------------------------------------------
extern "C" void kernel_launch(void* const* d_in, const int* in_sizes, int n_in,
                              void* d_out, int out_size)
{
    const float* input  = (const float*)d_in[0];
    const float* hx     = (const float*)d_in[1];
    const float* cx     = (const float*)d_in[2];
    const float* wih    = (const float*)d_in[3];
    const float* whh    = (const float*)d_in[4];
    const float* ln_i_w = (const float*)d_in[5];
    const float* ln_i_b = (const float*)d_in[6];
    const float* ln_h_w = (const float*)d_in[7];
    const float* ln_h_b = (const float*)d_in[8];
    const float* ln_c_w = (const float*)d_in[9];
    const float* ln_c_b = (const float*)d_in[10];
    float* out = (float*)d_out;

    cudaFuncSetAttribute(gemm_f16_kernel,
                         cudaFuncAttributeMaxDynamicSharedMemorySize, SMEM_TOTAL);

    __half *dA, *dH, *dWi, *dWh;
    cudaGetSymbolAddress((void**)&dA,  g_A);
    cudaGetSymbolAddress((void**)&dH,  g_H);
    cudaGetSymbolAddress((void**)&dWi, g_Wi);
    cudaGetSymbolAddress((void**)&dWh, g_Wh);

    cvt_fp16_kernel<<<dim3(296, 4), 256>>>(input, hx, wih, whh, dA, dH, dWi, dWh);

    dim3 grid(FH / BN, BATCH / BM, 2);
    gemm_f16_kernel<<<grid, 256, SMEM_TOTAL>>>(dA, dH, dWi, dWh);
    fuse_kernel<<<FUSE_CTAS, 256>>>(cx, ln_i_w, ln_i_b, ln_h_w, ln_h_b, ln_c_w, ln_c_b, out);
}

// round 14
// speedup vs baseline: 1.0090x; 1.0090x over previous
#include <cuda_runtime.h>
#include <cuda_fp16.h>
#include <math.h>
#include <stdint.h>

#define BATCH 8192
#define KDIM  1024
#define HDIM  1024
#define FH    4096

// Scratch: fp16 gate pre-activations + fp16 operand copies + per-row stats.
__device__ __half g_ig[(size_t)BATCH * FH];
__device__ __half g_hg[(size_t)BATCH * FH];
__device__ __half g_A [(size_t)BATCH * KDIM];
__device__ __half g_H [(size_t)BATCH * KDIM];
__device__ __half g_Wi[(size_t)FH * KDIM];
__device__ __half g_Wh[(size_t)FH * KDIM];
__device__ float g_sti[(size_t)BATCH * 2];   // (sum, sumsq) of igates per row
__device__ float g_sth[(size_t)BATCH * 2];   // (sum, sumsq) of hgates per row

// ---------------------------------------------------------------------------
// fp32 -> fp16 (RN) conversion (4 tensors) + stats-buffer zeroing (branch 4).
// ---------------------------------------------------------------------------
__global__ void __launch_bounds__(256)
cvt_fp16_kernel(const float* __restrict__ s0, const float* __restrict__ s1,
                const float* __restrict__ s2, const float* __restrict__ s3,
                __half* __restrict__ d0, __half* __restrict__ d1,
                __half* __restrict__ d2, __half* __restrict__ d3,
                float* __restrict__ sti, float* __restrict__ sth)
{
    if (blockIdx.y == 4) {
        int i = blockIdx.x * blockDim.x + threadIdx.x;
        int stride = gridDim.x * blockDim.x;
        for (; i < BATCH * 2; i += stride) {
            sti[i] = 0.f;
            sth[i] = 0.f;
        }
        return;
    }
    const float* src; __half* dst; int n4;
    switch (blockIdx.y) {
        case 0: src = s0; dst = d0; n4 = (BATCH * KDIM) / 4; break;
        case 1: src = s1; dst = d1; n4 = (BATCH * KDIM) / 4; break;
        case 2: src = s2; dst = d2; n4 = (FH * KDIM) / 4; break;
        default: src = s3; dst = d3; n4 = (FH * KDIM) / 4; break;
    }
    int i = blockIdx.x * blockDim.x + threadIdx.x;
    int stride = gridDim.x * blockDim.x;
    for (; i < n4; i += stride) {
        float4 v = ((const float4*)src)[i];
        __half2 lo = __floats2half2_rn(v.x, v.y);
        __half2 hi = __floats2half2_rn(v.z, v.w);
        uint2 p;
        p.x = *(uint32_t*)&lo;
        p.y = *(uint32_t*)&hi;
        ((uint2*)dst)[i] = p;
    }
}

// ---------------------------------------------------------------------------
// GEMM: out[m,n] = sum_k A[m,k] * W[n,k]  via mma.sync m16n8k16.f16 (fp32 acc)
// CTA tile 128x256, K-chunk 64, 3 stages, 8 warps (2x4), warp tile 64x64.
// Epilogue additionally reduces per-row (sum, sumsq) into stats via atomics.
// ---------------------------------------------------------------------------
#define BM 128
#define BN 256
#define KC 64
#define NCHUNK (KDIM / KC)                 // 16
#define ROWB  144
#define A_B   (BM * ROWB)
#define B_B   (BN * ROWB)
#define STAGE_BYTES (A_B + B_B)
#define SMEM_TOTAL (3 * STAGE_BYTES)
#define NTHREADS 256

__device__ __forceinline__ uint32_t smem_u32(const void* p) {
    uint32_t a;
    asm("{ .reg .u64 t; cvta.to.shared.u64 t, %1; cvt.u32.u64 %0, t; }" : "=r"(a) : "l"(p));
    return a;
}

__device__ __forceinline__ void cp16(uint32_t saddr, const void* g) {
    asm volatile("cp.async.cg.shared.global [%0], [%1], 16;" :: "r"(saddr), "l"(g));
}
#define CP_COMMIT() asm volatile("cp.async.commit_group;" ::: "memory")
#define CP_WAIT_1() asm volatile("cp.async.wait_group 1;" ::: "memory")

__device__ __forceinline__ void ldsm4(uint32_t& r0, uint32_t& r1, uint32_t& r2, uint32_t& r3,
                                      uint32_t addr) {
    asm volatile("ldmatrix.sync.aligned.m8n8.x4.shared.b16 {%0,%1,%2,%3}, [%4];"
                 : "=r"(r0), "=r"(r1), "=r"(r2), "=r"(r3) : "r"(addr));
}

__device__ __forceinline__ void mma_f16(float c[4], const uint32_t a[4], const uint32_t b[2]) {
    asm volatile(
        "mma.sync.aligned.m16n8k16.row.col.f32.f16.f16.f32 "
        "{%0,%1,%2,%3}, {%4,%5,%6,%7}, {%8,%9}, {%0,%1,%2,%3};"
        : "+f"(c[0]), "+f"(c[1]), "+f"(c[2]), "+f"(c[3])
        : "r"(a[0]), "r"(a[1]), "r"(a[2]), "r"(a[3]),
          "r"(b[0]), "r"(b[1]));
}

__global__ void __launch_bounds__(NTHREADS, 1)
gemm_f16_kernel(const __half* __restrict__ gA, const __half* __restrict__ gH,
                const __half* __restrict__ gWi, const __half* __restrict__ gWh)
{
    extern __shared__ char smem[];
    const uint32_t sbase = smem_u32(smem);

    const __half* A  = (blockIdx.z == 0) ? gA  : gH;
    const __half* W  = (blockIdx.z == 0) ? gWi : gWh;
    __half*      out = (blockIdx.z == 0) ? g_ig : g_hg;
    float*       stt = (blockIdx.z == 0) ? g_sti : g_sth;

    const int tid  = threadIdx.x;
    const int wid  = tid >> 5;
    const int lane = tid & 31;
    const int wm   = wid >> 2;
    const int wn   = wid & 3;
    const int m0   = blockIdx.y * BM;
    const int n0   = blockIdx.x * BN;

    const int ldrow = tid >> 3;
    const int ldc   = tid & 7;

    auto load_stage = [&](int st, int c) {
        const uint32_t sA = sbase + st * STAGE_BYTES;
        const uint32_t sB = sA + A_B;
        const int kt = c * KC;
        #pragma unroll
        for (int i = 0; i < 4; i++) {
            int row = ldrow + i * 32;
            cp16(sA + row * ROWB + ldc * 16,
                 &A[(size_t)(m0 + row) * KDIM + kt + ldc * 8]);
        }
        #pragma unroll
        for (int i = 0; i < 8; i++) {
            int row = ldrow + i * 32;
            cp16(sB + row * ROWB + ldc * 16,
                 &W[(size_t)(n0 + row) * KDIM + kt + ldc * 8]);
        }
    };

    const int lrow = lane & 15;
    const int lkof = (lane >> 4) * 16;
    uint32_t offA[4], offB[4];
    #pragma unroll
    for (int mt = 0; mt < 4; mt++)
        offA[mt] = (wm * 64 + mt * 16 + lrow) * ROWB + lkof;
    #pragma unroll
    for (int p = 0; p < 4; p++)
        offB[p] = (uint32_t)A_B + (wn * 64 + p * 16 + lrow) * ROWB + lkof;

    float acc[4][8][4];
    #pragma unroll
    for (int mt = 0; mt < 4; mt++)
        #pragma unroll
        for (int nt = 0; nt < 8; nt++)
            #pragma unroll
            for (int r = 0; r < 4; r++)
                acc[mt][nt][r] = 0.f;

    load_stage(0, 0); CP_COMMIT();
    load_stage(1, 1); CP_COMMIT();

    int st = 0;
    for (int c = 0; c < NCHUNK; c++) {
        CP_WAIT_1();
        __syncthreads();

        int st2 = st + 2; if (st2 >= 3) st2 -= 3;
        if (c + 2 < NCHUNK) load_stage(st2, c + 2);
        CP_COMMIT();

        const uint32_t sb = sbase + st * STAGE_BYTES;

        #pragma unroll
        for (int ks = 0; ks < 4; ks++) {
            const uint32_t kb = ks * 32;

            uint32_t af[4][4];
            #pragma unroll
            for (int mt = 0; mt < 4; mt++)
                ldsm4(af[mt][0], af[mt][1], af[mt][2], af[mt][3], sb + offA[mt] + kb);
            uint32_t bf[8][2];
            #pragma unroll
            for (int p = 0; p < 4; p++)
                ldsm4(bf[2*p][0], bf[2*p+1][0], bf[2*p][1], bf[2*p+1][1],
                      sb + offB[p] + kb);
            #pragma unroll
            for (int mt = 0; mt < 4; mt++)
                #pragma unroll
                for (int nt = 0; nt < 8; nt++)
                    mma_f16(acc[mt][nt], af[mt], bf[nt]);
        }

        if (++st >= 3) st -= 3;
    }

    // epilogue: fp16 stores + per-row (sum, sumsq) partials -> atomicAdd
    #pragma unroll
    for (int mt = 0; mt < 4; mt++) {
        int row0 = m0 + wm * 64 + mt * 16 + (lane >> 2);
        float s0 = 0.f, q0 = 0.f, s1 = 0.f, q1 = 0.f;
        #pragma unroll
        for (int nt = 0; nt < 8; nt++) {
            int col0 = n0 + wn * 64 + nt * 8 + 2 * (lane & 3);
            float a0 = acc[mt][nt][0], a1 = acc[mt][nt][1];
            float a2 = acc[mt][nt][2], a3 = acc[mt][nt][3];
            __half2 v0 = __floats2half2_rn(a0, a1);
            __half2 v1 = __floats2half2_rn(a2, a3);
            *(__half2*)&out[(size_t)row0 * FH + col0]       = v0;
            *(__half2*)&out[(size_t)(row0 + 8) * FH + col0] = v1;
            s0 += a0 + a1; q0 += a0 * a0 + a1 * a1;
            s1 += a2 + a3; q1 += a2 * a2 + a3 * a3;
        }
        // reduce across the 4 lanes sharing each row (lane&3 = column nibble)
        s0 += __shfl_down_sync(0xffffffffu, s0, 1);
        q0 += __shfl_down_sync(0xffffffffu, q0, 1);
        s1 += __shfl_down_sync(0xffffffffu, s1, 1);
        q1 += __shfl_down_sync(0xffffffffu, q1, 1);
        s0 += __shfl_down_sync(0xffffffffu, s0, 2);
        q0 += __shfl_down_sync(0xffffffffu, q0, 2);
        s1 += __shfl_down_sync(0xffffffffu, s1, 2);
        q1 += __shfl_down_sync(0xffffffffu, q1, 2);
        if ((lane & 3) == 0) {
            atomicAdd(&stt[2 * row0],           s0);
            atomicAdd(&stt[2 * row0 + 1],       q0);
            atomicAdd(&stt[2 * (row0 + 8)],     s1);
            atomicAdd(&stt[2 * (row0 + 8) + 1], q1);
        }
    }
}

// ---------------------------------------------------------------------------
// Fused LayerNorm + LSTM gates + cell LayerNorm. Row stats come precomputed
// from the GEMM epilogue -> no big block reduction here.
// ---------------------------------------------------------------------------
__device__ __forceinline__ float sigmoidf_(float x) {
    return 1.f / (1.f + expf(-x));
}

__device__ __forceinline__ float4 unpack4(uint2 u) {
    __half2 h0 = *(__half2*)&u.x;
    __half2 h1 = *(__half2*)&u.y;
    float2 f0 = __half22float2(h0);
    float2 f1 = __half22float2(h1);
    return make_float4(f0.x, f0.y, f1.x, f1.y);
}

__device__ __forceinline__ float2 block_sum2(float2 v, float2* sh) {
    #pragma unroll
    for (int o = 16; o > 0; o >>= 1) {
        v.x += __shfl_down_sync(0xffffffffu, v.x, o);
        v.y += __shfl_down_sync(0xffffffffu, v.y, o);
    }
    int lane = threadIdx.x & 31, w = threadIdx.x >> 5;
    if (lane == 0) sh[w] = v;
    __syncthreads();
    if (w == 0) {
        float2 t = (lane < 8) ? sh[lane] : make_float2(0.f, 0.f);
        #pragma unroll
        for (int o = 4; o > 0; o >>= 1) {
            t.x += __shfl_down_sync(0xffffffffu, t.x, o);
            t.y += __shfl_down_sync(0xffffffffu, t.y, o);
        }
        if (lane == 0) sh[0] = t;
    }
    __syncthreads();
    return sh[0];
}

__global__ void __launch_bounds__(256)
fuse_kernel(const float* __restrict__ cx,
            const float* __restrict__ ln_i_w, const float* __restrict__ ln_i_b,
            const float* __restrict__ ln_h_w, const float* __restrict__ ln_h_b,
            const float* __restrict__ ln_c_w, const float* __restrict__ ln_c_b,
            float* __restrict__ out)
{
    const int b   = blockIdx.x;
    const int tid = threadIdx.x;
    const uint2* ig2 = (const uint2*)(g_ig + (size_t)b * FH);
    const uint2* hg2 = (const uint2*)(g_hg + (size_t)b * FH);

    __shared__ float2 red_c[8];

    // precomputed row stats (uniform loads, L2/L1 resident)
    float2 sti = ((const float2*)g_sti)[b];
    float2 sth = ((const float2*)g_sth)[b];
    const float inv_fh = 1.f / (float)FH;
    float mu_i = sti.x * inv_fh;
    float rs_i = rsqrtf(sti.y * inv_fh - mu_i * mu_i + 1e-5f);
    float mu_h = sth.x * inv_fh;
    float rs_h = rsqrtf(sth.y * inv_fh - mu_h * mu_h + 1e-5f);

    float4 c4 = ((const float4*)cx)[(size_t)b * 256 + tid];

    // gate p for h = 4t..4t+3  (p: 0=i, 1=f, 2=g, 3=o)
    float4 g[4];
    #pragma unroll
    for (int p = 0; p < 4; p++) {
        int j = tid + p * 256;
        float4 a = unpack4(ig2[j]);
        float4 c = unpack4(hg2[j]);
        float4 wi = ((const float4*)ln_i_w)[j], bi = ((const float4*)ln_i_b)[j];
        float4 wh = ((const float4*)ln_h_w)[j], bh = ((const float4*)ln_h_b)[j];
        g[p].x = (a.x - mu_i) * rs_i * wi.x + bi.x + (c.x - mu_h) * rs_h * wh.x + bh.x;
        g[p].y = (a.y - mu_i) * rs_i * wi.y + bi.y + (c.y - mu_h) * rs_h * wh.y + bh.y;
        g[p].z = (a.z - mu_i) * rs_i * wi.z + bi.z + (c.z - mu_h) * rs_h * wh.z + bh.z;
        g[p].w = (a.w - mu_i) * rs_i * wi.w + bi.w + (c.w - mu_h) * rs_h * wh.w + bh.w;
    }

    float4 cv;
    cv.x = sigmoidf_(g[1].x) * c4.x + sigmoidf_(g[0].x) * tanhf(g[2].x);
    cv.y = sigmoidf_(g[1].y) * c4.y + sigmoidf_(g[0].y) * tanhf(g[2].y);
    cv.z = sigmoidf_(g[1].z) * c4.z + sigmoidf_(g[0].z) * tanhf(g[2].z);
    cv.w = sigmoidf_(g[1].w) * c4.w + sigmoidf_(g[0].w) * tanhf(g[2].w);

    float2 sc = make_float2(cv.x + cv.y + cv.z + cv.w,
                            cv.x*cv.x + cv.y*cv.y + cv.z*cv.z + cv.w*cv.w);
    float2 rc = block_sum2(sc, red_c);
    const float inv_h = 1.f / (float)HDIM;
    float mu_c = rc.x * inv_h;
    float rs_c = rsqrtf(rc.y * inv_h - mu_c * mu_c + 1e-5f);

    float4 wc = ((const float4*)ln_c_w)[tid], bc = ((const float4*)ln_c_b)[tid];
    float4 cy, hy;
    cy.x = (cv.x - mu_c) * rs_c * wc.x + bc.x;  hy.x = sigmoidf_(g[3].x) * tanhf(cy.x);
    cy.y = (cv.y - mu_c) * rs_c * wc.y + bc.y;  hy.y = sigmoidf_(g[3].y) * tanhf(cy.y);
    cy.z = (cv.z - mu_c) * rs_c * wc.z + bc.z;  hy.z = sigmoidf_(g[3].z) * tanhf(cy.z);
    cy.w = (cv.w - mu_c) * rs_c * wc.w + bc.w;  hy.w = sigmoidf_(g[3].w) * tanhf(cy.w);

    ((float4*)out)[(size_t)b * 256 + tid] = hy;
    ((float4*)out)[(size_t)BATCH * 256 + (size_t)b * 256 + tid] = cy;
}

// ---------------------------------------------------------------------------
extern "C" void kernel_launch(void* const* d_in, const int* in_sizes, int n_in,
                              void* d_out, int out_size)
{
    const float* input  = (const float*)d_in[0];
    const float* hx     = (const float*)d_in[1];
    const float* cx     = (const float*)d_in[2];
    const float* wih    = (const float*)d_in[3];
    const float* whh    = (const float*)d_in[4];
    const float* ln_i_w = (const float*)d_in[5];
    const float* ln_i_b = (const float*)d_in[6];
    const float* ln_h_w = (const float*)d_in[7];
    const float* ln_h_b = (const float*)d_in[8];
    const float* ln_c_w = (const float*)d_in[9];
    const float* ln_c_b = (const float*)d_in[10];
    float* out = (float*)d_out;

    cudaFuncSetAttribute(gemm_f16_kernel,
                         cudaFuncAttributeMaxDynamicSharedMemorySize, SMEM_TOTAL);

    __half *dA, *dH, *dWi, *dWh;
    float *dSti, *dSth;
    cudaGetSymbolAddress((void**)&dA,  g_A);
    cudaGetSymbolAddress((void**)&dH,  g_H);
    cudaGetSymbolAddress((void**)&dWi, g_Wi);
    cudaGetSymbolAddress((void**)&dWh, g_Wh);
    cudaGetSymbolAddress((void**)&dSti, g_sti);
    cudaGetSymbolAddress((void**)&dSth, g_sth);

    cvt_fp16_kernel<<<dim3(296, 5), 256>>>(input, hx, wih, whh,
                                           dA, dH, dWi, dWh, dSti, dSth);

    dim3 grid(FH / BN, BATCH / BM, 2);
    gemm_f16_kernel<<<grid, 256, SMEM_TOTAL>>>(dA, dH, dWi, dWh);
    fuse_kernel<<<BATCH, 256>>>(cx, ln_i_w, ln_i_b, ln_h_w, ln_h_b, ln_c_w, ln_c_b, out);
}

// round 15
// speedup vs baseline: 1.0438x; 1.0345x over previous
#include <cuda_runtime.h>
#include <cuda_fp16.h>
#include <math.h>
#include <stdint.h>

#define BATCH 8192
#define KDIM  1024
#define HDIM  1024
#define FH    4096

// Scratch: fp16 gate pre-activations + fp16 operand copies.
__device__ __half g_ig[(size_t)BATCH * FH];
__device__ __half g_hg[(size_t)BATCH * FH];
__device__ __half g_A [(size_t)BATCH * KDIM];
__device__ __half g_H [(size_t)BATCH * KDIM];
__device__ __half g_Wi[(size_t)FH * KDIM];
__device__ __half g_Wh[(size_t)FH * KDIM];

// ---------------------------------------------------------------------------
// fp32 -> fp16 (RN) conversion, all 4 tensors in one launch.
// ---------------------------------------------------------------------------
__global__ void __launch_bounds__(256)
cvt_fp16_kernel(const float* __restrict__ s0, const float* __restrict__ s1,
                const float* __restrict__ s2, const float* __restrict__ s3,
                __half* __restrict__ d0, __half* __restrict__ d1,
                __half* __restrict__ d2, __half* __restrict__ d3)
{
    const float* src; __half* dst; int n4;
    switch (blockIdx.y) {
        case 0: src = s0; dst = d0; n4 = (BATCH * KDIM) / 4; break;
        case 1: src = s1; dst = d1; n4 = (BATCH * KDIM) / 4; break;
        case 2: src = s2; dst = d2; n4 = (FH * KDIM) / 4; break;
        default: src = s3; dst = d3; n4 = (FH * KDIM) / 4; break;
    }
    int i = blockIdx.x * blockDim.x + threadIdx.x;
    int stride = gridDim.x * blockDim.x;
    for (; i < n4; i += stride) {
        float4 v = ((const float4*)src)[i];
        __half2 lo = __floats2half2_rn(v.x, v.y);
        __half2 hi = __floats2half2_rn(v.z, v.w);
        uint2 p;
        p.x = *(uint32_t*)&lo;
        p.y = *(uint32_t*)&hi;
        ((uint2*)dst)[i] = p;
    }
}

// ---------------------------------------------------------------------------
// GEMM: out[m,n] = sum_k A[m,k] * W[n,k]  via mma.sync m16n8k16.f16 (fp32 acc)
// CTA tile 128x256, K-chunk 64, 3 stages, 8 warps (2x4), warp tile 64x64.
// At the measured legacy tensor-pipe MAC floor: frozen (R12 configuration).
// ---------------------------------------------------------------------------
#define BM 128
#define BN 256
#define KC 64
#define NCHUNK (KDIM / KC)                 // 16
#define ROWB  144
#define A_B   (BM * ROWB)
#define B_B   (BN * ROWB)
#define STAGE_BYTES (A_B + B_B)
#define SMEM_TOTAL (3 * STAGE_BYTES)
#define NTHREADS 256

__device__ __forceinline__ uint32_t smem_u32(const void* p) {
    uint32_t a;
    asm("{ .reg .u64 t; cvta.to.shared.u64 t, %1; cvt.u32.u64 %0, t; }" : "=r"(a) : "l"(p));
    return a;
}

__device__ __forceinline__ void cp16(uint32_t saddr, const void* g) {
    asm volatile("cp.async.cg.shared.global [%0], [%1], 16;" :: "r"(saddr), "l"(g));
}
#define CP_COMMIT() asm volatile("cp.async.commit_group;" ::: "memory")
#define CP_WAIT_1() asm volatile("cp.async.wait_group 1;" ::: "memory")

__device__ __forceinline__ void ldsm4(uint32_t& r0, uint32_t& r1, uint32_t& r2, uint32_t& r3,
                                      uint32_t addr) {
    asm volatile("ldmatrix.sync.aligned.m8n8.x4.shared.b16 {%0,%1,%2,%3}, [%4];"
                 : "=r"(r0), "=r"(r1), "=r"(r2), "=r"(r3) : "r"(addr));
}

__device__ __forceinline__ void mma_f16(float c[4], const uint32_t a[4], const uint32_t b[2]) {
    asm volatile(
        "mma.sync.aligned.m16n8k16.row.col.f32.f16.f16.f32 "
        "{%0,%1,%2,%3}, {%4,%5,%6,%7}, {%8,%9}, {%0,%1,%2,%3};"
        : "+f"(c[0]), "+f"(c[1]), "+f"(c[2]), "+f"(c[3])
        : "r"(a[0]), "r"(a[1]), "r"(a[2]), "r"(a[3]),
          "r"(b[0]), "r"(b[1]));
}

__global__ void __launch_bounds__(NTHREADS, 1)
gemm_f16_kernel(const __half* __restrict__ gA, const __half* __restrict__ gH,
                const __half* __restrict__ gWi, const __half* __restrict__ gWh)
{
    extern __shared__ char smem[];
    const uint32_t sbase = smem_u32(smem);

    const __half* A  = (blockIdx.z == 0) ? gA  : gH;
    const __half* W  = (blockIdx.z == 0) ? gWi : gWh;
    __half*      out = (blockIdx.z == 0) ? g_ig : g_hg;

    const int tid  = threadIdx.x;
    const int wid  = tid >> 5;
    const int lane = tid & 31;
    const int wm   = wid >> 2;
    const int wn   = wid & 3;
    const int m0   = blockIdx.y * BM;
    const int n0   = blockIdx.x * BN;

    const int ldrow = tid >> 3;
    const int ldc   = tid & 7;

    auto load_stage = [&](int st, int c) {
        const uint32_t sA = sbase + st * STAGE_BYTES;
        const uint32_t sB = sA + A_B;
        const int kt = c * KC;
        #pragma unroll
        for (int i = 0; i < 4; i++) {
            int row = ldrow + i * 32;
            cp16(sA + row * ROWB + ldc * 16,
                 &A[(size_t)(m0 + row) * KDIM + kt + ldc * 8]);
        }
        #pragma unroll
        for (int i = 0; i < 8; i++) {
            int row = ldrow + i * 32;
            cp16(sB + row * ROWB + ldc * 16,
                 &W[(size_t)(n0 + row) * KDIM + kt + ldc * 8]);
        }
    };

    const int lrow = lane & 15;
    const int lkof = (lane >> 4) * 16;
    uint32_t offA[4], offB[4];
    #pragma unroll
    for (int mt = 0; mt < 4; mt++)
        offA[mt] = (wm * 64 + mt * 16 + lrow) * ROWB + lkof;
    #pragma unroll
    for (int p = 0; p < 4; p++)
        offB[p] = (uint32_t)A_B + (wn * 64 + p * 16 + lrow) * ROWB + lkof;

    float acc[4][8][4];
    #pragma unroll
    for (int mt = 0; mt < 4; mt++)
        #pragma unroll
        for (int nt = 0; nt < 8; nt++)
            #pragma unroll
            for (int r = 0; r < 4; r++)
                acc[mt][nt][r] = 0.f;

    load_stage(0, 0); CP_COMMIT();
    load_stage(1, 1); CP_COMMIT();

    int st = 0;
    for (int c = 0; c < NCHUNK; c++) {
        CP_WAIT_1();
        __syncthreads();

        int st2 = st + 2; if (st2 >= 3) st2 -= 3;
        if (c + 2 < NCHUNK) load_stage(st2, c + 2);
        CP_COMMIT();

        const uint32_t sb = sbase + st * STAGE_BYTES;

        #pragma unroll
        for (int ks = 0; ks < 4; ks++) {
            const uint32_t kb = ks * 32;

            uint32_t af[4][4];
            #pragma unroll
            for (int mt = 0; mt < 4; mt++)
                ldsm4(af[mt][0], af[mt][1], af[mt][2], af[mt][3], sb + offA[mt] + kb);
            uint32_t bf[8][2];
            #pragma unroll
            for (int p = 0; p < 4; p++)
                ldsm4(bf[2*p][0], bf[2*p+1][0], bf[2*p][1], bf[2*p+1][1],
                      sb + offB[p] + kb);
            #pragma unroll
            for (int mt = 0; mt < 4; mt++)
                #pragma unroll
                for (int nt = 0; nt < 8; nt++)
                    mma_f16(acc[mt][nt], af[mt], bf[nt]);
        }

        if (++st >= 3) st -= 3;
    }

    // epilogue: fp16 stores
    #pragma unroll
    for (int mt = 0; mt < 4; mt++) {
        int row0 = m0 + wm * 64 + mt * 16 + (lane >> 2);
        #pragma unroll
        for (int nt = 0; nt < 8; nt++) {
            int col0 = n0 + wn * 64 + nt * 8 + 2 * (lane & 3);
            __half2 v0 = __floats2half2_rn(acc[mt][nt][0], acc[mt][nt][1]);
            __half2 v1 = __floats2half2_rn(acc[mt][nt][2], acc[mt][nt][3]);
            *(__half2*)&out[(size_t)row0 * FH + col0]       = v0;
            *(__half2*)&out[(size_t)(row0 + 8) * FH + col0] = v1;
        }
    }
}

// ---------------------------------------------------------------------------
// Fused LayerNorm + LSTM gates + cell LayerNorm (R12 structure), with native
// tanh.approx.f32 for tanh AND sigmoid (sigmoid(x)=0.5*tanh(0.5x)+0.5).
// ---------------------------------------------------------------------------
__device__ __forceinline__ float tanh_fast(float x) {
    float y;
    asm("tanh.approx.f32 %0, %1;" : "=f"(y) : "f"(x));
    return y;
}

__device__ __forceinline__ float sigmoid_fast(float x) {
    return fmaf(tanh_fast(0.5f * x), 0.5f, 0.5f);
}

__device__ __forceinline__ float4 unpack4(uint2 u) {
    __half2 h0 = *(__half2*)&u.x;
    __half2 h1 = *(__half2*)&u.y;
    float2 f0 = __half22float2(h0);
    float2 f1 = __half22float2(h1);
    return make_float4(f0.x, f0.y, f1.x, f1.y);
}

__device__ __forceinline__ float4 block_sum4(float4 v, float4* sh) {
    #pragma unroll
    for (int o = 16; o > 0; o >>= 1) {
        v.x += __shfl_down_sync(0xffffffffu, v.x, o);
        v.y += __shfl_down_sync(0xffffffffu, v.y, o);
        v.z += __shfl_down_sync(0xffffffffu, v.z, o);
        v.w += __shfl_down_sync(0xffffffffu, v.w, o);
    }
    int lane = threadIdx.x & 31, w = threadIdx.x >> 5;
    if (lane == 0) sh[w] = v;
    __syncthreads();
    if (w == 0) {
        float4 t = (lane < 8) ? sh[lane] : make_float4(0.f, 0.f, 0.f, 0.f);
        #pragma unroll
        for (int o = 4; o > 0; o >>= 1) {
            t.x += __shfl_down_sync(0xffffffffu, t.x, o);
            t.y += __shfl_down_sync(0xffffffffu, t.y, o);
            t.z += __shfl_down_sync(0xffffffffu, t.z, o);
            t.w += __shfl_down_sync(0xffffffffu, t.w, o);
        }
        if (lane == 0) sh[0] = t;
    }
    __syncthreads();
    return sh[0];
}

__device__ __forceinline__ float2 block_sum2(float2 v, float2* sh) {
    #pragma unroll
    for (int o = 16; o > 0; o >>= 1) {
        v.x += __shfl_down_sync(0xffffffffu, v.x, o);
        v.y += __shfl_down_sync(0xffffffffu, v.y, o);
    }
    int lane = threadIdx.x & 31, w = threadIdx.x >> 5;
    if (lane == 0) sh[w] = v;
    __syncthreads();
    if (w == 0) {
        float2 t = (lane < 8) ? sh[lane] : make_float2(0.f, 0.f);
        #pragma unroll
        for (int o = 4; o > 0; o >>= 1) {
            t.x += __shfl_down_sync(0xffffffffu, t.x, o);
            t.y += __shfl_down_sync(0xffffffffu, t.y, o);
        }
        if (lane == 0) sh[0] = t;
    }
    __syncthreads();
    return sh[0];
}

__global__ void __launch_bounds__(256)
fuse_kernel(const float* __restrict__ cx,
            const float* __restrict__ ln_i_w, const float* __restrict__ ln_i_b,
            const float* __restrict__ ln_h_w, const float* __restrict__ ln_h_b,
            const float* __restrict__ ln_c_w, const float* __restrict__ ln_c_b,
            float* __restrict__ out)
{
    const int b   = blockIdx.x;
    const int tid = threadIdx.x;
    const uint2* ig2 = (const uint2*)(g_ig + (size_t)b * FH);
    const uint2* hg2 = (const uint2*)(g_hg + (size_t)b * FH);

    __shared__ float4 red4[8];
    __shared__ float2 red_c[8];

    uint2 pi[4], ph[4];
    float4 s = make_float4(0.f, 0.f, 0.f, 0.f);
    #pragma unroll
    for (int p = 0; p < 4; p++) {
        int j = tid + p * 256;
        pi[p] = ig2[j];
        ph[p] = hg2[j];
        float4 a = unpack4(pi[p]);
        float4 c = unpack4(ph[p]);
        s.x += a.x + a.y + a.z + a.w;
        s.y += a.x*a.x + a.y*a.y + a.z*a.z + a.w*a.w;
        s.z += c.x + c.y + c.z + c.w;
        s.w += c.x*c.x + c.y*c.y + c.z*c.z + c.w*c.w;
    }
    float4 r = block_sum4(s, red4);

    const float inv_fh = 1.f / (float)FH;
    float mu_i = r.x * inv_fh;
    float rs_i = rsqrtf(r.y * inv_fh - mu_i * mu_i + 1e-5f);
    float mu_h = r.z * inv_fh;
    float rs_h = rsqrtf(r.w * inv_fh - mu_h * mu_h + 1e-5f);

    float4 g[4];
    #pragma unroll
    for (int p = 0; p < 4; p++) {
        int j = tid + p * 256;
        float4 wi = ((const float4*)ln_i_w)[j], bi = ((const float4*)ln_i_b)[j];
        float4 wh = ((const float4*)ln_h_w)[j], bh = ((const float4*)ln_h_b)[j];
        float4 a = unpack4(pi[p]);
        float4 c = unpack4(ph[p]);
        g[p].x = (a.x - mu_i) * rs_i * wi.x + bi.x + (c.x - mu_h) * rs_h * wh.x + bh.x;
        g[p].y = (a.y - mu_i) * rs_i * wi.y + bi.y + (c.y - mu_h) * rs_h * wh.y + bh.y;
        g[p].z = (a.z - mu_i) * rs_i * wi.z + bi.z + (c.z - mu_h) * rs_h * wh.z + bh.z;
        g[p].w = (a.w - mu_i) * rs_i * wi.w + bi.w + (c.w - mu_h) * rs_h * wh.w + bh.w;
    }

    float4 c4 = ((const float4*)cx)[(size_t)b * 256 + tid];

    float4 cv;
    cv.x = sigmoid_fast(g[1].x) * c4.x + sigmoid_fast(g[0].x) * tanh_fast(g[2].x);
    cv.y = sigmoid_fast(g[1].y) * c4.y + sigmoid_fast(g[0].y) * tanh_fast(g[2].y);
    cv.z = sigmoid_fast(g[1].z) * c4.z + sigmoid_fast(g[0].z) * tanh_fast(g[2].z);
    cv.w = sigmoid_fast(g[1].w) * c4.w + sigmoid_fast(g[0].w) * tanh_fast(g[2].w);

    float2 sc = make_float2(cv.x + cv.y + cv.z + cv.w,
                            cv.x*cv.x + cv.y*cv.y + cv.z*cv.z + cv.w*cv.w);
    float2 rc = block_sum2(sc, red_c);
    const float inv_h = 1.f / (float)HDIM;
    float mu_c = rc.x * inv_h;
    float rs_c = rsqrtf(rc.y * inv_h - mu_c * mu_c + 1e-5f);

    float4 wc = ((const float4*)ln_c_w)[tid], bc = ((const float4*)ln_c_b)[tid];
    float4 cy, hy;
    cy.x = (cv.x - mu_c) * rs_c * wc.x + bc.x;  hy.x = sigmoid_fast(g[3].x) * tanh_fast(cy.x);
    cy.y = (cv.y - mu_c) * rs_c * wc.y + bc.y;  hy.y = sigmoid_fast(g[3].y) * tanh_fast(cy.y);
    cy.z = (cv.z - mu_c) * rs_c * wc.z + bc.z;  hy.z = sigmoid_fast(g[3].z) * tanh_fast(cy.z);
    cy.w = (cv.w - mu_c) * rs_c * wc.w + bc.w;  hy.w = sigmoid_fast(g[3].w) * tanh_fast(cy.w);

    ((float4*)out)[(size_t)b * 256 + tid] = hy;
    ((float4*)out)[(size_t)BATCH * 256 + (size_t)b * 256 + tid] = cy;
}

// ---------------------------------------------------------------------------
extern "C" void kernel_launch(void* const* d_in, const int* in_sizes, int n_in,
                              void* d_out, int out_size)
{
    const float* input  = (const float*)d_in[0];
    const float* hx     = (const float*)d_in[1];
    const float* cx     = (const float*)d_in[2];
    const float* wih    = (const float*)d_in[3];
    const float* whh    = (const float*)d_in[4];
    const float* ln_i_w = (const float*)d_in[5];
    const float* ln_i_b = (const float*)d_in[6];
    const float* ln_h_w = (const float*)d_in[7];
    const float* ln_h_b = (const float*)d_in[8];
    const float* ln_c_w = (const float*)d_in[9];
    const float* ln_c_b = (const float*)d_in[10];
    float* out = (float*)d_out;

    cudaFuncSetAttribute(gemm_f16_kernel,
                         cudaFuncAttributeMaxDynamicSharedMemorySize, SMEM_TOTAL);

    __half *dA, *dH, *dWi, *dWh;
    cudaGetSymbolAddress((void**)&dA,  g_A);
    cudaGetSymbolAddress((void**)&dH,  g_H);
    cudaGetSymbolAddress((void**)&dWi, g_Wi);
    cudaGetSymbolAddress((void**)&dWh, g_Wh);

    cvt_fp16_kernel<<<dim3(296, 4), 256>>>(input, hx, wih, whh, dA, dH, dWi, dWh);

    dim3 grid(FH / BN, BATCH / BM, 2);
    gemm_f16_kernel<<<grid, 256, SMEM_TOTAL>>>(dA, dH, dWi, dWh);
    fuse_kernel<<<BATCH, 256>>>(cx, ln_i_w, ln_i_b, ln_h_w, ln_h_b, ln_c_w, ln_c_b, out);
}

// round 16
// speedup vs baseline: 1.0472x; 1.0033x over previous
#include <cuda_runtime.h>
#include <cuda_fp16.h>
#include <math.h>
#include <stdint.h>

#define BATCH 8192
#define KDIM  1024
#define HDIM  1024
#define FH    4096

// Scratch: fp16 gate pre-activations + fp16 operand copies.
__device__ __half g_ig[(size_t)BATCH * FH];
__device__ __half g_hg[(size_t)BATCH * FH];
__device__ __half g_A [(size_t)BATCH * KDIM];
__device__ __half g_H [(size_t)BATCH * KDIM];
__device__ __half g_Wi[(size_t)FH * KDIM];
__device__ __half g_Wh[(size_t)FH * KDIM];

// ---------------------------------------------------------------------------
// fp32 -> fp16 (RN) conversion, all 4 tensors in one launch. (Frozen.)
// ---------------------------------------------------------------------------
__global__ void __launch_bounds__(256)
cvt_fp16_kernel(const float* __restrict__ s0, const float* __restrict__ s1,
                const float* __restrict__ s2, const float* __restrict__ s3,
                __half* __restrict__ d0, __half* __restrict__ d1,
                __half* __restrict__ d2, __half* __restrict__ d3)
{
    const float* src; __half* dst; int n4;
    switch (blockIdx.y) {
        case 0: src = s0; dst = d0; n4 = (BATCH * KDIM) / 4; break;
        case 1: src = s1; dst = d1; n4 = (BATCH * KDIM) / 4; break;
        case 2: src = s2; dst = d2; n4 = (FH * KDIM) / 4; break;
        default: src = s3; dst = d3; n4 = (FH * KDIM) / 4; break;
    }
    int i = blockIdx.x * blockDim.x + threadIdx.x;
    int stride = gridDim.x * blockDim.x;
    for (; i < n4; i += stride) {
        float4 v = ((const float4*)src)[i];
        __half2 lo = __floats2half2_rn(v.x, v.y);
        __half2 hi = __floats2half2_rn(v.z, v.w);
        uint2 p;
        p.x = *(uint32_t*)&lo;
        p.y = *(uint32_t*)&hi;
        ((uint2*)dst)[i] = p;
    }
}

// ---------------------------------------------------------------------------
// GEMM: out[m,n] = sum_k A[m,k] * W[n,k]  via mma.sync m16n8k16.f16 (fp32 acc)
// CTA tile 128x256, K-chunk 64, 3 stages, 8 warps (2x4), warp tile 64x64.
// At the measured legacy tensor-pipe MAC floor: frozen.
// ---------------------------------------------------------------------------
#define BM 128
#define BN 256
#define KC 64
#define NCHUNK (KDIM / KC)                 // 16
#define ROWB  144
#define A_B   (BM * ROWB)
#define B_B   (BN * ROWB)
#define STAGE_BYTES (A_B + B_B)
#define SMEM_TOTAL (3 * STAGE_BYTES)
#define NTHREADS 256

__device__ __forceinline__ uint32_t smem_u32(const void* p) {
    uint32_t a;
    asm("{ .reg .u64 t; cvta.to.shared.u64 t, %1; cvt.u32.u64 %0, t; }" : "=r"(a) : "l"(p));
    return a;
}

__device__ __forceinline__ void cp16(uint32_t saddr, const void* g) {
    asm volatile("cp.async.cg.shared.global [%0], [%1], 16;" :: "r"(saddr), "l"(g));
}
#define CP_COMMIT() asm volatile("cp.async.commit_group;" ::: "memory")
#define CP_WAIT_1() asm volatile("cp.async.wait_group 1;" ::: "memory")

__device__ __forceinline__ void ldsm4(uint32_t& r0, uint32_t& r1, uint32_t& r2, uint32_t& r3,
                                      uint32_t addr) {
    asm volatile("ldmatrix.sync.aligned.m8n8.x4.shared.b16 {%0,%1,%2,%3}, [%4];"
                 : "=r"(r0), "=r"(r1), "=r"(r2), "=r"(r3) : "r"(addr));
}

__device__ __forceinline__ void mma_f16(float c[4], const uint32_t a[4], const uint32_t b[2]) {
    asm volatile(
        "mma.sync.aligned.m16n8k16.row.col.f32.f16.f16.f32 "
        "{%0,%1,%2,%3}, {%4,%5,%6,%7}, {%8,%9}, {%0,%1,%2,%3};"
        : "+f"(c[0]), "+f"(c[1]), "+f"(c[2]), "+f"(c[3])
        : "r"(a[0]), "r"(a[1]), "r"(a[2]), "r"(a[3]),
          "r"(b[0]), "r"(b[1]));
}

__global__ void __launch_bounds__(NTHREADS, 1)
gemm_f16_kernel(const __half* __restrict__ gA, const __half* __restrict__ gH,
                const __half* __restrict__ gWi, const __half* __restrict__ gWh)
{
    extern __shared__ char smem[];
    const uint32_t sbase = smem_u32(smem);

    const __half* A  = (blockIdx.z == 0) ? gA  : gH;
    const __half* W  = (blockIdx.z == 0) ? gWi : gWh;
    __half*      out = (blockIdx.z == 0) ? g_ig : g_hg;

    const int tid  = threadIdx.x;
    const int wid  = tid >> 5;
    const int lane = tid & 31;
    const int wm   = wid >> 2;
    const int wn   = wid & 3;
    const int m0   = blockIdx.y * BM;
    const int n0   = blockIdx.x * BN;

    const int ldrow = tid >> 3;
    const int ldc   = tid & 7;

    auto load_stage = [&](int st, int c) {
        const uint32_t sA = sbase + st * STAGE_BYTES;
        const uint32_t sB = sA + A_B;
        const int kt = c * KC;
        #pragma unroll
        for (int i = 0; i < 4; i++) {
            int row = ldrow + i * 32;
            cp16(sA + row * ROWB + ldc * 16,
                 &A[(size_t)(m0 + row) * KDIM + kt + ldc * 8]);
        }
        #pragma unroll
        for (int i = 0; i < 8; i++) {
            int row = ldrow + i * 32;
            cp16(sB + row * ROWB + ldc * 16,
                 &W[(size_t)(n0 + row) * KDIM + kt + ldc * 8]);
        }
    };

    const int lrow = lane & 15;
    const int lkof = (lane >> 4) * 16;
    uint32_t offA[4], offB[4];
    #pragma unroll
    for (int mt = 0; mt < 4; mt++)
        offA[mt] = (wm * 64 + mt * 16 + lrow) * ROWB + lkof;
    #pragma unroll
    for (int p = 0; p < 4; p++)
        offB[p] = (uint32_t)A_B + (wn * 64 + p * 16 + lrow) * ROWB + lkof;

    float acc[4][8][4];
    #pragma unroll
    for (int mt = 0; mt < 4; mt++)
        #pragma unroll
        for (int nt = 0; nt < 8; nt++)
            #pragma unroll
            for (int r = 0; r < 4; r++)
                acc[mt][nt][r] = 0.f;

    load_stage(0, 0); CP_COMMIT();
    load_stage(1, 1); CP_COMMIT();

    int st = 0;
    for (int c = 0; c < NCHUNK; c++) {
        CP_WAIT_1();
        __syncthreads();

        int st2 = st + 2; if (st2 >= 3) st2 -= 3;
        if (c + 2 < NCHUNK) load_stage(st2, c + 2);
        CP_COMMIT();

        const uint32_t sb = sbase + st * STAGE_BYTES;

        #pragma unroll
        for (int ks = 0; ks < 4; ks++) {
            const uint32_t kb = ks * 32;

            uint32_t af[4][4];
            #pragma unroll
            for (int mt = 0; mt < 4; mt++)
                ldsm4(af[mt][0], af[mt][1], af[mt][2], af[mt][3], sb + offA[mt] + kb);
            uint32_t bf[8][2];
            #pragma unroll
            for (int p = 0; p < 4; p++)
                ldsm4(bf[2*p][0], bf[2*p+1][0], bf[2*p][1], bf[2*p+1][1],
                      sb + offB[p] + kb);
            #pragma unroll
            for (int mt = 0; mt < 4; mt++)
                #pragma unroll
                for (int nt = 0; nt < 8; nt++)
                    mma_f16(acc[mt][nt], af[mt], bf[nt]);
        }

        if (++st >= 3) st -= 3;
    }

    // epilogue: fp16 stores
    #pragma unroll
    for (int mt = 0; mt < 4; mt++) {
        int row0 = m0 + wm * 64 + mt * 16 + (lane >> 2);
        #pragma unroll
        for (int nt = 0; nt < 8; nt++) {
            int col0 = n0 + wn * 64 + nt * 8 + 2 * (lane & 3);
            __half2 v0 = __floats2half2_rn(acc[mt][nt][0], acc[mt][nt][1]);
            __half2 v1 = __floats2half2_rn(acc[mt][nt][2], acc[mt][nt][3]);
            *(__half2*)&out[(size_t)row0 * FH + col0]       = v0;
            *(__half2*)&out[(size_t)(row0 + 8) * FH + col0] = v1;
        }
    }
}

// ---------------------------------------------------------------------------
// Fused LayerNorm + LSTM gates + cell LayerNorm.
// TWO rows per CTA, fully unrolled (no rotation): batched front loads,
// dual-row reductions (halved barriers/row), LN params loaded once per pair.
// ---------------------------------------------------------------------------
__device__ __forceinline__ float tanh_fast(float x) {
    float y;
    asm("tanh.approx.f32 %0, %1;" : "=f"(y) : "f"(x));
    return y;
}

__device__ __forceinline__ float sigmoid_fast(float x) {
    return fmaf(tanh_fast(0.5f * x), 0.5f, 0.5f);
}

__device__ __forceinline__ float4 unpack4(uint2 u) {
    __half2 h0 = *(__half2*)&u.x;
    __half2 h1 = *(__half2*)&u.y;
    float2 f0 = __half22float2(h0);
    float2 f1 = __half22float2(h1);
    return make_float4(f0.x, f0.y, f1.x, f1.y);
}

// dual float4 block reduction (one barrier structure for 8 values)
__device__ __forceinline__ void block_sum4x2(float4& a, float4& b,
                                             float4* shA, float4* shB) {
    #pragma unroll
    for (int o = 16; o > 0; o >>= 1) {
        a.x += __shfl_down_sync(0xffffffffu, a.x, o);
        a.y += __shfl_down_sync(0xffffffffu, a.y, o);
        a.z += __shfl_down_sync(0xffffffffu, a.z, o);
        a.w += __shfl_down_sync(0xffffffffu, a.w, o);
        b.x += __shfl_down_sync(0xffffffffu, b.x, o);
        b.y += __shfl_down_sync(0xffffffffu, b.y, o);
        b.z += __shfl_down_sync(0xffffffffu, b.z, o);
        b.w += __shfl_down_sync(0xffffffffu, b.w, o);
    }
    int lane = threadIdx.x & 31, w = threadIdx.x >> 5;
    if (lane == 0) { shA[w] = a; shB[w] = b; }
    __syncthreads();
    if (w == 0) {
        float4 ta = (lane < 8) ? shA[lane] : make_float4(0.f, 0.f, 0.f, 0.f);
        float4 tb = (lane < 8) ? shB[lane] : make_float4(0.f, 0.f, 0.f, 0.f);
        #pragma unroll
        for (int o = 4; o > 0; o >>= 1) {
            ta.x += __shfl_down_sync(0xffffffffu, ta.x, o);
            ta.y += __shfl_down_sync(0xffffffffu, ta.y, o);
            ta.z += __shfl_down_sync(0xffffffffu, ta.z, o);
            ta.w += __shfl_down_sync(0xffffffffu, ta.w, o);
            tb.x += __shfl_down_sync(0xffffffffu, tb.x, o);
            tb.y += __shfl_down_sync(0xffffffffu, tb.y, o);
            tb.z += __shfl_down_sync(0xffffffffu, tb.z, o);
            tb.w += __shfl_down_sync(0xffffffffu, tb.w, o);
        }
        if (lane == 0) { shA[0] = ta; shB[0] = tb; }
    }
    __syncthreads();
    a = shA[0];
    b = shB[0];
}

__device__ __forceinline__ float4 block_sum4(float4 v, float4* sh) {
    #pragma unroll
    for (int o = 16; o > 0; o >>= 1) {
        v.x += __shfl_down_sync(0xffffffffu, v.x, o);
        v.y += __shfl_down_sync(0xffffffffu, v.y, o);
        v.z += __shfl_down_sync(0xffffffffu, v.z, o);
        v.w += __shfl_down_sync(0xffffffffu, v.w, o);
    }
    int lane = threadIdx.x & 31, w = threadIdx.x >> 5;
    if (lane == 0) sh[w] = v;
    __syncthreads();
    if (w == 0) {
        float4 t = (lane < 8) ? sh[lane] : make_float4(0.f, 0.f, 0.f, 0.f);
        #pragma unroll
        for (int o = 4; o > 0; o >>= 1) {
            t.x += __shfl_down_sync(0xffffffffu, t.x, o);
            t.y += __shfl_down_sync(0xffffffffu, t.y, o);
            t.z += __shfl_down_sync(0xffffffffu, t.z, o);
            t.w += __shfl_down_sync(0xffffffffu, t.w, o);
        }
        if (lane == 0) sh[0] = t;
    }
    __syncthreads();
    return sh[0];
}

__global__ void __launch_bounds__(256)
fuse_kernel(const float* __restrict__ cx,
            const float* __restrict__ ln_i_w, const float* __restrict__ ln_i_b,
            const float* __restrict__ ln_h_w, const float* __restrict__ ln_h_b,
            const float* __restrict__ ln_c_w, const float* __restrict__ ln_c_b,
            float* __restrict__ out)
{
    const int b0  = blockIdx.x * 2;
    const int tid = threadIdx.x;
    const uint2* ig0 = (const uint2*)(g_ig + (size_t)b0 * FH);
    const uint2* hg0 = (const uint2*)(g_hg + (size_t)b0 * FH);
    const uint2* ig1 = (const uint2*)(g_ig + (size_t)(b0 + 1) * FH);
    const uint2* hg1 = (const uint2*)(g_hg + (size_t)(b0 + 1) * FH);

    __shared__ float4 redA[8], redB[8], redC[8];

    // both rows' gates, packed fp16 in registers
    uint2 pi[2][4], ph[2][4];
    float4 sa = make_float4(0.f, 0.f, 0.f, 0.f);   // row0: sum_i, sq_i, sum_h, sq_h
    float4 sb = make_float4(0.f, 0.f, 0.f, 0.f);   // row1
    #pragma unroll
    for (int p = 0; p < 4; p++) {
        int j = tid + p * 256;
        pi[0][p] = ig0[j];  ph[0][p] = hg0[j];
        pi[1][p] = ig1[j];  ph[1][p] = hg1[j];
        float4 a0 = unpack4(pi[0][p]), c0 = unpack4(ph[0][p]);
        float4 a1 = unpack4(pi[1][p]), c1 = unpack4(ph[1][p]);
        sa.x += a0.x + a0.y + a0.z + a0.w;
        sa.y += a0.x*a0.x + a0.y*a0.y + a0.z*a0.z + a0.w*a0.w;
        sa.z += c0.x + c0.y + c0.z + c0.w;
        sa.w += c0.x*c0.x + c0.y*c0.y + c0.z*c0.z + c0.w*c0.w;
        sb.x += a1.x + a1.y + a1.z + a1.w;
        sb.y += a1.x*a1.x + a1.y*a1.y + a1.z*a1.z + a1.w*a1.w;
        sb.z += c1.x + c1.y + c1.z + c1.w;
        sb.w += c1.x*c1.x + c1.y*c1.y + c1.z*c1.z + c1.w*c1.w;
    }
    block_sum4x2(sa, sb, redA, redB);

    const float inv_fh = 1.f / (float)FH;
    float mu_i[2], rs_i[2], mu_h[2], rs_h[2];
    mu_i[0] = sa.x * inv_fh;
    rs_i[0] = rsqrtf(sa.y * inv_fh - mu_i[0] * mu_i[0] + 1e-5f);
    mu_h[0] = sa.z * inv_fh;
    rs_h[0] = rsqrtf(sa.w * inv_fh - mu_h[0] * mu_h[0] + 1e-5f);
    mu_i[1] = sb.x * inv_fh;
    rs_i[1] = rsqrtf(sb.y * inv_fh - mu_i[1] * mu_i[1] + 1e-5f);
    mu_h[1] = sb.z * inv_fh;
    rs_h[1] = rsqrtf(sb.w * inv_fh - mu_h[1] * mu_h[1] + 1e-5f);

    // gate LN: params loaded ONCE, used for both rows
    float4 g[2][4];
    #pragma unroll
    for (int p = 0; p < 4; p++) {
        int j = tid + p * 256;
        float4 wi = ((const float4*)ln_i_w)[j], bi = ((const float4*)ln_i_b)[j];
        float4 wh = ((const float4*)ln_h_w)[j], bh = ((const float4*)ln_h_b)[j];
        #pragma unroll
        for (int r = 0; r < 2; r++) {
            float4 a = unpack4(pi[r][p]);
            float4 c = unpack4(ph[r][p]);
            g[r][p].x = (a.x - mu_i[r]) * rs_i[r] * wi.x + bi.x
                      + (c.x - mu_h[r]) * rs_h[r] * wh.x + bh.x;
            g[r][p].y = (a.y - mu_i[r]) * rs_i[r] * wi.y + bi.y
                      + (c.y - mu_h[r]) * rs_h[r] * wh.y + bh.y;
            g[r][p].z = (a.z - mu_i[r]) * rs_i[r] * wi.z + bi.z
                      + (c.z - mu_h[r]) * rs_h[r] * wh.z + bh.z;
            g[r][p].w = (a.w - mu_i[r]) * rs_i[r] * wi.w + bi.w
                      + (c.w - mu_h[r]) * rs_h[r] * wh.w + bh.w;
        }
    }

    // cell update for both rows; pack both rows' stats into one float4
    float4 cv[2];
    float4 sc = make_float4(0.f, 0.f, 0.f, 0.f);   // (s0, q0, s1, q1)
    #pragma unroll
    for (int r = 0; r < 2; r++) {
        float4 c4 = ((const float4*)cx)[(size_t)(b0 + r) * 256 + tid];
        cv[r].x = sigmoid_fast(g[r][1].x) * c4.x + sigmoid_fast(g[r][0].x) * tanh_fast(g[r][2].x);
        cv[r].y = sigmoid_fast(g[r][1].y) * c4.y + sigmoid_fast(g[r][0].y) * tanh_fast(g[r][2].y);
        cv[r].z = sigmoid_fast(g[r][1].z) * c4.z + sigmoid_fast(g[r][0].z) * tanh_fast(g[r][2].z);
        cv[r].w = sigmoid_fast(g[r][1].w) * c4.w + sigmoid_fast(g[r][0].w) * tanh_fast(g[r][2].w);
        float s = cv[r].x + cv[r].y + cv[r].z + cv[r].w;
        float q = cv[r].x*cv[r].x + cv[r].y*cv[r].y + cv[r].z*cv[r].z + cv[r].w*cv[r].w;
        if (r == 0) { sc.x = s; sc.y = q; } else { sc.z = s; sc.w = q; }
    }
    float4 rc = block_sum4(sc, redC);

    const float inv_h = 1.f / (float)HDIM;
    float mu_c[2], rs_c[2];
    mu_c[0] = rc.x * inv_h;
    rs_c[0] = rsqrtf(rc.y * inv_h - mu_c[0] * mu_c[0] + 1e-5f);
    mu_c[1] = rc.z * inv_h;
    rs_c[1] = rsqrtf(rc.w * inv_h - mu_c[1] * mu_c[1] + 1e-5f);

    float4 wc = ((const float4*)ln_c_w)[tid], bc = ((const float4*)ln_c_b)[tid];
    #pragma unroll
    for (int r = 0; r < 2; r++) {
        const int b = b0 + r;
        float4 cy, hy;
        cy.x = (cv[r].x - mu_c[r]) * rs_c[r] * wc.x + bc.x;
        hy.x = sigmoid_fast(g[r][3].x) * tanh_fast(cy.x);
        cy.y = (cv[r].y - mu_c[r]) * rs_c[r] * wc.y + bc.y;
        hy.y = sigmoid_fast(g[r][3].y) * tanh_fast(cy.y);
        cy.z = (cv[r].z - mu_c[r]) * rs_c[r] * wc.z + bc.z;
        hy.z = sigmoid_fast(g[r][3].z) * tanh_fast(cy.z);
        cy.w = (cv[r].w - mu_c[r]) * rs_c[r] * wc.w + bc.w;
        hy.w = sigmoid_fast(g[r][3].w) * tanh_fast(cy.w);

        ((float4*)out)[(size_t)b * 256 + tid] = hy;
        ((float4*)out)[(size_t)BATCH * 256 + (size_t)b * 256 + tid] = cy;
    }
}

// ---------------------------------------------------------------------------
extern "C" void kernel_launch(void* const* d_in, const int* in_sizes, int n_in,
                              void* d_out, int out_size)
{
    const float* input  = (const float*)d_in[0];
    const float* hx     = (const float*)d_in[1];
    const float* cx     = (const float*)d_in[2];
    const float* wih    = (const float*)d_in[3];
    const float* whh    = (const float*)d_in[4];
    const float* ln_i_w = (const float*)d_in[5];
    const float* ln_i_b = (const float*)d_in[6];
    const float* ln_h_w = (const float*)d_in[7];
    const float* ln_h_b = (const float*)d_in[8];
    const float* ln_c_w = (const float*)d_in[9];
    const float* ln_c_b = (const float*)d_in[10];
    float* out = (float*)d_out;

    cudaFuncSetAttribute(gemm_f16_kernel,
                         cudaFuncAttributeMaxDynamicSharedMemorySize, SMEM_TOTAL);

    __half *dA, *dH, *dWi, *dWh;
    cudaGetSymbolAddress((void**)&dA,  g_A);
    cudaGetSymbolAddress((void**)&dH,  g_H);
    cudaGetSymbolAddress((void**)&dWi, g_Wi);
    cudaGetSymbolAddress((void**)&dWh, g_Wh);

    cvt_fp16_kernel<<<dim3(296, 4), 256>>>(input, hx, wih, whh, dA, dH, dWi, dWh);

    dim3 grid(FH / BN, BATCH / BM, 2);
    gemm_f16_kernel<<<grid, 256, SMEM_TOTAL>>>(dA, dH, dWi, dWh);
    fuse_kernel<<<BATCH / 2, 256>>>(cx, ln_i_w, ln_i_b, ln_h_w, ln_h_b, ln_c_w, ln_c_b, out);
}

// round 17
// speedup vs baseline: 1.0636x; 1.0157x over previous
#include <cuda_runtime.h>
#include <cuda_fp16.h>
#include <math.h>
#include <stdint.h>

#define BATCH 8192
#define KDIM  1024
#define HDIM  1024
#define FH    4096

// Scratch: fp16 gate pre-activations + fp16 operand copies.
__device__ __half g_ig[(size_t)BATCH * FH];
__device__ __half g_hg[(size_t)BATCH * FH];
__device__ __half g_A [(size_t)BATCH * KDIM];
__device__ __half g_H [(size_t)BATCH * KDIM];
__device__ __half g_Wi[(size_t)FH * KDIM];
__device__ __half g_Wh[(size_t)FH * KDIM];

// ---------------------------------------------------------------------------
// fp32 -> fp16 (RN) conversion, two tensors per launch (activation + weight).
// ---------------------------------------------------------------------------
__global__ void __launch_bounds__(256)
cvt2_fp16_kernel(const float* __restrict__ s0, const float* __restrict__ s1,
                 __half* __restrict__ d0, __half* __restrict__ d1,
                 int n0, int n1)
{
    const float* src; __half* dst; int n4;
    if (blockIdx.y == 0) { src = s0; dst = d0; n4 = n0; }
    else                 { src = s1; dst = d1; n4 = n1; }
    int i = blockIdx.x * blockDim.x + threadIdx.x;
    int stride = gridDim.x * blockDim.x;
    for (; i < n4; i += stride) {
        float4 v = ((const float4*)src)[i];
        __half2 lo = __floats2half2_rn(v.x, v.y);
        __half2 hi = __floats2half2_rn(v.z, v.w);
        uint2 p;
        p.x = *(uint32_t*)&lo;
        p.y = *(uint32_t*)&hi;
        ((uint2*)dst)[i] = p;
    }
}

// ---------------------------------------------------------------------------
// GEMM: out[m,n] = sum_k A[m,k] * W[n,k]  via mma.sync m16n8k16.f16 (fp32 acc)
// CTA tile 128x256, K-chunk 64, 3 stages, 8 warps (2x4), warp tile 64x64.
// At the measured legacy tensor-pipe MAC floor: frozen.
// ---------------------------------------------------------------------------
#define BM 128
#define BN 256
#define KC 64
#define NCHUNK (KDIM / KC)                 // 16
#define ROWB  144
#define A_B   (BM * ROWB)
#define B_B   (BN * ROWB)
#define STAGE_BYTES (A_B + B_B)
#define SMEM_TOTAL (3 * STAGE_BYTES)
#define NTHREADS 256

__device__ __forceinline__ uint32_t smem_u32(const void* p) {
    uint32_t a;
    asm("{ .reg .u64 t; cvta.to.shared.u64 t, %1; cvt.u32.u64 %0, t; }" : "=r"(a) : "l"(p));
    return a;
}

__device__ __forceinline__ void cp16(uint32_t saddr, const void* g) {
    asm volatile("cp.async.cg.shared.global [%0], [%1], 16;" :: "r"(saddr), "l"(g));
}
#define CP_COMMIT() asm volatile("cp.async.commit_group;" ::: "memory")
#define CP_WAIT_1() asm volatile("cp.async.wait_group 1;" ::: "memory")

__device__ __forceinline__ void ldsm4(uint32_t& r0, uint32_t& r1, uint32_t& r2, uint32_t& r3,
                                      uint32_t addr) {
    asm volatile("ldmatrix.sync.aligned.m8n8.x4.shared.b16 {%0,%1,%2,%3}, [%4];"
                 : "=r"(r0), "=r"(r1), "=r"(r2), "=r"(r3) : "r"(addr));
}

__device__ __forceinline__ void mma_f16(float c[4], const uint32_t a[4], const uint32_t b[2]) {
    asm volatile(
        "mma.sync.aligned.m16n8k16.row.col.f32.f16.f16.f32 "
        "{%0,%1,%2,%3}, {%4,%5,%6,%7}, {%8,%9}, {%0,%1,%2,%3};"
        : "+f"(c[0]), "+f"(c[1]), "+f"(c[2]), "+f"(c[3])
        : "r"(a[0]), "r"(a[1]), "r"(a[2]), "r"(a[3]),
          "r"(b[0]), "r"(b[1]));
}

__global__ void __launch_bounds__(NTHREADS, 1)
gemm_f16_kernel(const __half* __restrict__ A, const __half* __restrict__ W,
                __half* __restrict__ out)
{
    extern __shared__ char smem[];
    const uint32_t sbase = smem_u32(smem);

    const int tid  = threadIdx.x;
    const int wid  = tid >> 5;
    const int lane = tid & 31;
    const int wm   = wid >> 2;
    const int wn   = wid & 3;
    const int m0   = blockIdx.y * BM;
    const int n0   = blockIdx.x * BN;

    const int ldrow = tid >> 3;
    const int ldc   = tid & 7;

    auto load_stage = [&](int st, int c) {
        const uint32_t sA = sbase + st * STAGE_BYTES;
        const uint32_t sB = sA + A_B;
        const int kt = c * KC;
        #pragma unroll
        for (int i = 0; i < 4; i++) {
            int row = ldrow + i * 32;
            cp16(sA + row * ROWB + ldc * 16,
                 &A[(size_t)(m0 + row) * KDIM + kt + ldc * 8]);
        }
        #pragma unroll
        for (int i = 0; i < 8; i++) {
            int row = ldrow + i * 32;
            cp16(sB + row * ROWB + ldc * 16,
                 &W[(size_t)(n0 + row) * KDIM + kt + ldc * 8]);
        }
    };

    const int lrow = lane & 15;
    const int lkof = (lane >> 4) * 16;
    uint32_t offA[4], offB[4];
    #pragma unroll
    for (int mt = 0; mt < 4; mt++)
        offA[mt] = (wm * 64 + mt * 16 + lrow) * ROWB + lkof;
    #pragma unroll
    for (int p = 0; p < 4; p++)
        offB[p] = (uint32_t)A_B + (wn * 64 + p * 16 + lrow) * ROWB + lkof;

    float acc[4][8][4];
    #pragma unroll
    for (int mt = 0; mt < 4; mt++)
        #pragma unroll
        for (int nt = 0; nt < 8; nt++)
            #pragma unroll
            for (int r = 0; r < 4; r++)
                acc[mt][nt][r] = 0.f;

    load_stage(0, 0); CP_COMMIT();
    load_stage(1, 1); CP_COMMIT();

    int st = 0;
    for (int c = 0; c < NCHUNK; c++) {
        CP_WAIT_1();
        __syncthreads();

        int st2 = st + 2; if (st2 >= 3) st2 -= 3;
        if (c + 2 < NCHUNK) load_stage(st2, c + 2);
        CP_COMMIT();

        const uint32_t sb = sbase + st * STAGE_BYTES;

        #pragma unroll
        for (int ks = 0; ks < 4; ks++) {
            const uint32_t kb = ks * 32;

            uint32_t af[4][4];
            #pragma unroll
            for (int mt = 0; mt < 4; mt++)
                ldsm4(af[mt][0], af[mt][1], af[mt][2], af[mt][3], sb + offA[mt] + kb);
            uint32_t bf[8][2];
            #pragma unroll
            for (int p = 0; p < 4; p++)
                ldsm4(bf[2*p][0], bf[2*p+1][0], bf[2*p][1], bf[2*p+1][1],
                      sb + offB[p] + kb);
            #pragma unroll
            for (int mt = 0; mt < 4; mt++)
                #pragma unroll
                for (int nt = 0; nt < 8; nt++)
                    mma_f16(acc[mt][nt], af[mt], bf[nt]);
        }

        if (++st >= 3) st -= 3;
    }

    // epilogue: fp16 stores
    #pragma unroll
    for (int mt = 0; mt < 4; mt++) {
        int row0 = m0 + wm * 64 + mt * 16 + (lane >> 2);
        #pragma unroll
        for (int nt = 0; nt < 8; nt++) {
            int col0 = n0 + wn * 64 + nt * 8 + 2 * (lane & 3);
            __half2 v0 = __floats2half2_rn(acc[mt][nt][0], acc[mt][nt][1]);
            __half2 v1 = __floats2half2_rn(acc[mt][nt][2], acc[mt][nt][3]);
            *(__half2*)&out[(size_t)row0 * FH + col0]       = v0;
            *(__half2*)&out[(size_t)(row0 + 8) * FH + col0] = v1;
        }
    }
}

// ---------------------------------------------------------------------------
// Fused LayerNorm + LSTM gates + cell LayerNorm (R16: 2 rows/CTA, unchanged).
// ---------------------------------------------------------------------------
__device__ __forceinline__ float tanh_fast(float x) {
    float y;
    asm("tanh.approx.f32 %0, %1;" : "=f"(y) : "f"(x));
    return y;
}

__device__ __forceinline__ float sigmoid_fast(float x) {
    return fmaf(tanh_fast(0.5f * x), 0.5f, 0.5f);
}

__device__ __forceinline__ float4 unpack4(uint2 u) {
    __half2 h0 = *(__half2*)&u.x;
    __half2 h1 = *(__half2*)&u.y;
    float2 f0 = __half22float2(h0);
    float2 f1 = __half22float2(h1);
    return make_float4(f0.x, f0.y, f1.x, f1.y);
}

__device__ __forceinline__ void block_sum4x2(float4& a, float4& b,
                                             float4* shA, float4* shB) {
    #pragma unroll
    for (int o = 16; o > 0; o >>= 1) {
        a.x += __shfl_down_sync(0xffffffffu, a.x, o);
        a.y += __shfl_down_sync(0xffffffffu, a.y, o);
        a.z += __shfl_down_sync(0xffffffffu, a.z, o);
        a.w += __shfl_down_sync(0xffffffffu, a.w, o);
        b.x += __shfl_down_sync(0xffffffffu, b.x, o);
        b.y += __shfl_down_sync(0xffffffffu, b.y, o);
        b.z += __shfl_down_sync(0xffffffffu, b.z, o);
        b.w += __shfl_down_sync(0xffffffffu, b.w, o);
    }
    int lane = threadIdx.x & 31, w = threadIdx.x >> 5;
    if (lane == 0) { shA[w] = a; shB[w] = b; }
    __syncthreads();
    if (w == 0) {
        float4 ta = (lane < 8) ? shA[lane] : make_float4(0.f, 0.f, 0.f, 0.f);
        float4 tb = (lane < 8) ? shB[lane] : make_float4(0.f, 0.f, 0.f, 0.f);
        #pragma unroll
        for (int o = 4; o > 0; o >>= 1) {
            ta.x += __shfl_down_sync(0xffffffffu, ta.x, o);
            ta.y += __shfl_down_sync(0xffffffffu, ta.y, o);
            ta.z += __shfl_down_sync(0xffffffffu, ta.z, o);
            ta.w += __shfl_down_sync(0xffffffffu, ta.w, o);
            tb.x += __shfl_down_sync(0xffffffffu, tb.x, o);
            tb.y += __shfl_down_sync(0xffffffffu, tb.y, o);
            tb.z += __shfl_down_sync(0xffffffffu, tb.z, o);
            tb.w += __shfl_down_sync(0xffffffffu, tb.w, o);
        }
        if (lane == 0) { shA[0] = ta; shB[0] = tb; }
    }
    __syncthreads();
    a = shA[0];
    b = shB[0];
}

__device__ __forceinline__ float4 block_sum4(float4 v, float4* sh) {
    #pragma unroll
    for (int o = 16; o > 0; o >>= 1) {
        v.x += __shfl_down_sync(0xffffffffu, v.x, o);
        v.y += __shfl_down_sync(0xffffffffu, v.y, o);
        v.z += __shfl_down_sync(0xffffffffu, v.z, o);
        v.w += __shfl_down_sync(0xffffffffu, v.w, o);
    }
    int lane = threadIdx.x & 31, w = threadIdx.x >> 5;
    if (lane == 0) sh[w] = v;
    __syncthreads();
    if (w == 0) {
        float4 t = (lane < 8) ? sh[lane] : make_float4(0.f, 0.f, 0.f, 0.f);
        #pragma unroll
        for (int o = 4; o > 0; o >>= 1) {
            t.x += __shfl_down_sync(0xffffffffu, t.x, o);
            t.y += __shfl_down_sync(0xffffffffu, t.y, o);
            t.z += __shfl_down_sync(0xffffffffu, t.z, o);
            t.w += __shfl_down_sync(0xffffffffu, t.w, o);
        }
        if (lane == 0) sh[0] = t;
    }
    __syncthreads();
    return sh[0];
}

__global__ void __launch_bounds__(256)
fuse_kernel(const float* __restrict__ cx,
            const float* __restrict__ ln_i_w, const float* __restrict__ ln_i_b,
            const float* __restrict__ ln_h_w, const float* __restrict__ ln_h_b,
            const float* __restrict__ ln_c_w, const float* __restrict__ ln_c_b,
            float* __restrict__ out)
{
    const int b0  = blockIdx.x * 2;
    const int tid = threadIdx.x;
    const uint2* ig0 = (const uint2*)(g_ig + (size_t)b0 * FH);
    const uint2* hg0 = (const uint2*)(g_hg + (size_t)b0 * FH);
    const uint2* ig1 = (const uint2*)(g_ig + (size_t)(b0 + 1) * FH);
    const uint2* hg1 = (const uint2*)(g_hg + (size_t)(b0 + 1) * FH);

    __shared__ float4 redA[8], redB[8], redC[8];

    uint2 pi[2][4], ph[2][4];
    float4 sa = make_float4(0.f, 0.f, 0.f, 0.f);
    float4 sb = make_float4(0.f, 0.f, 0.f, 0.f);
    #pragma unroll
    for (int p = 0; p < 4; p++) {
        int j = tid + p * 256;
        pi[0][p] = ig0[j];  ph[0][p] = hg0[j];
        pi[1][p] = ig1[j];  ph[1][p] = hg1[j];
        float4 a0 = unpack4(pi[0][p]), c0 = unpack4(ph[0][p]);
        float4 a1 = unpack4(pi[1][p]), c1 = unpack4(ph[1][p]);
        sa.x += a0.x + a0.y + a0.z + a0.w;
        sa.y += a0.x*a0.x + a0.y*a0.y + a0.z*a0.z + a0.w*a0.w;
        sa.z += c0.x + c0.y + c0.z + c0.w;
        sa.w += c0.x*c0.x + c0.y*c0.y + c0.z*c0.z + c0.w*c0.w;
        sb.x += a1.x + a1.y + a1.z + a1.w;
        sb.y += a1.x*a1.x + a1.y*a1.y + a1.z*a1.z + a1.w*a1.w;
        sb.z += c1.x + c1.y + c1.z + c1.w;
        sb.w += c1.x*c1.x + c1.y*c1.y + c1.z*c1.z + c1.w*c1.w;
    }
    block_sum4x2(sa, sb, redA, redB);

    const float inv_fh = 1.f / (float)FH;
    float mu_i[2], rs_i[2], mu_h[2], rs_h[2];
    mu_i[0] = sa.x * inv_fh;
    rs_i[0] = rsqrtf(sa.y * inv_fh - mu_i[0] * mu_i[0] + 1e-5f);
    mu_h[0] = sa.z * inv_fh;
    rs_h[0] = rsqrtf(sa.w * inv_fh - mu_h[0] * mu_h[0] + 1e-5f);
    mu_i[1] = sb.x * inv_fh;
    rs_i[1] = rsqrtf(sb.y * inv_fh - mu_i[1] * mu_i[1] + 1e-5f);
    mu_h[1] = sb.z * inv_fh;
    rs_h[1] = rsqrtf(sb.w * inv_fh - mu_h[1] * mu_h[1] + 1e-5f);

    float4 g[2][4];
    #pragma unroll
    for (int p = 0; p < 4; p++) {
        int j = tid + p * 256;
        float4 wi = ((const float4*)ln_i_w)[j], bi = ((const float4*)ln_i_b)[j];
        float4 wh = ((const float4*)ln_h_w)[j], bh = ((const float4*)ln_h_b)[j];
        #pragma unroll
        for (int r = 0; r < 2; r++) {
            float4 a = unpack4(pi[r][p]);
            float4 c = unpack4(ph[r][p]);
            g[r][p].x = (a.x - mu_i[r]) * rs_i[r] * wi.x + bi.x
                      + (c.x - mu_h[r]) * rs_h[r] * wh.x + bh.x;
            g[r][p].y = (a.y - mu_i[r]) * rs_i[r] * wi.y + bi.y
                      + (c.y - mu_h[r]) * rs_h[r] * wh.y + bh.y;
            g[r][p].z = (a.z - mu_i[r]) * rs_i[r] * wi.z + bi.z
                      + (c.z - mu_h[r]) * rs_h[r] * wh.z + bh.z;
            g[r][p].w = (a.w - mu_i[r]) * rs_i[r] * wi.w + bi.w
                      + (c.w - mu_h[r]) * rs_h[r] * wh.w + bh.w;
        }
    }

    float4 cv[2];
    float4 sc = make_float4(0.f, 0.f, 0.f, 0.f);
    #pragma unroll
    for (int r = 0; r < 2; r++) {
        float4 c4 = ((const float4*)cx)[(size_t)(b0 + r) * 256 + tid];
        cv[r].x = sigmoid_fast(g[r][1].x) * c4.x + sigmoid_fast(g[r][0].x) * tanh_fast(g[r][2].x);
        cv[r].y = sigmoid_fast(g[r][1].y) * c4.y + sigmoid_fast(g[r][0].y) * tanh_fast(g[r][2].y);
        cv[r].z = sigmoid_fast(g[r][1].z) * c4.z + sigmoid_fast(g[r][0].z) * tanh_fast(g[r][2].z);
        cv[r].w = sigmoid_fast(g[r][1].w) * c4.w + sigmoid_fast(g[r][0].w) * tanh_fast(g[r][2].w);
        float s = cv[r].x + cv[r].y + cv[r].z + cv[r].w;
        float q = cv[r].x*cv[r].x + cv[r].y*cv[r].y + cv[r].z*cv[r].z + cv[r].w*cv[r].w;
        if (r == 0) { sc.x = s; sc.y = q; } else { sc.z = s; sc.w = q; }
    }
    float4 rc = block_sum4(sc, redC);

    const float inv_h = 1.f / (float)HDIM;
    float mu_c[2], rs_c[2];
    mu_c[0] = rc.x * inv_h;
    rs_c[0] = rsqrtf(rc.y * inv_h - mu_c[0] * mu_c[0] + 1e-5f);
    mu_c[1] = rc.z * inv_h;
    rs_c[1] = rsqrtf(rc.w * inv_h - mu_c[1] * mu_c[1] + 1e-5f);

    float4 wc = ((const float4*)ln_c_w)[tid], bc = ((const float4*)ln_c_b)[tid];
    #pragma unroll
    for (int r = 0; r < 2; r++) {
        const int b = b0 + r;
        float4 cy, hy;
        cy.x = (cv[r].x - mu_c[r]) * rs_c[r] * wc.x + bc.x;
        hy.x = sigmoid_fast(g[r][3].x) * tanh_fast(cy.x);
        cy.y = (cv[r].y - mu_c[r]) * rs_c[r] * wc.y + bc.y;
        hy.y = sigmoid_fast(g[r][3].y) * tanh_fast(cy.y);
        cy.z = (cv[r].z - mu_c[r]) * rs_c[r] * wc.z + bc.z;
        hy.z = sigmoid_fast(g[r][3].z) * tanh_fast(cy.z);
        cy.w = (cv[r].w - mu_c[r]) * rs_c[r] * wc.w + bc.w;
        hy.w = sigmoid_fast(g[r][3].w) * tanh_fast(cy.w);

        ((float4*)out)[(size_t)b * 256 + tid] = hy;
        ((float4*)out)[(size_t)BATCH * 256 + (size_t)b * 256 + tid] = cy;
    }
}

// ---------------------------------------------------------------------------
// Launch: fork-join graph. Stream 1 converts H/Wh under gemm(A,Wi), then runs
// gemm(H,Wh) concurrently; join before fuse.
// ---------------------------------------------------------------------------
extern "C" void kernel_launch(void* const* d_in, const int* in_sizes, int n_in,
                              void* d_out, int out_size)
{
    const float* input  = (const float*)d_in[0];
    const float* hx     = (const float*)d_in[1];
    const float* cx     = (const float*)d_in[2];
    const float* wih    = (const float*)d_in[3];
    const float* whh    = (const float*)d_in[4];
    const float* ln_i_w = (const float*)d_in[5];
    const float* ln_i_b = (const float*)d_in[6];
    const float* ln_h_w = (const float*)d_in[7];
    const float* ln_h_b = (const float*)d_in[8];
    const float* ln_c_w = (const float*)d_in[9];
    const float* ln_c_b = (const float*)d_in[10];
    float* out = (float*)d_out;

    static cudaStream_t s1 = nullptr;
    static cudaEvent_t ev_fork = nullptr, ev_join = nullptr;
    if (s1 == nullptr) {
        cudaStreamCreateWithFlags(&s1, cudaStreamNonBlocking);
        cudaEventCreateWithFlags(&ev_fork, cudaEventDisableTiming);
        cudaEventCreateWithFlags(&ev_join, cudaEventDisableTiming);
        cudaFuncSetAttribute(gemm_f16_kernel,
                             cudaFuncAttributeMaxDynamicSharedMemorySize, SMEM_TOTAL);
    }

    __half *dA, *dH, *dWi, *dWh, *dIG, *dHG;
    cudaGetSymbolAddress((void**)&dA,  g_A);
    cudaGetSymbolAddress((void**)&dH,  g_H);
    cudaGetSymbolAddress((void**)&dWi, g_Wi);
    cudaGetSymbolAddress((void**)&dWh, g_Wh);
    cudaGetSymbolAddress((void**)&dIG, g_ig);
    cudaGetSymbolAddress((void**)&dHG, g_hg);

    const int nA = (BATCH * KDIM) / 4;
    const int nW = (FH * KDIM) / 4;
    dim3 grid(FH / BN, BATCH / BM);

    // stream0: cvt(input, wih) -> fork -> gemm(A, Wi)
    cvt2_fp16_kernel<<<dim3(296, 2), 256>>>(input, wih, dA, dWi, nA, nW);
    cudaEventRecord(ev_fork, 0);
    gemm_f16_kernel<<<grid, NTHREADS, SMEM_TOTAL>>>(dA, dWi, dIG);

    // stream1: wait fork -> cvt(hx, whh) (overlaps gemm0) -> gemm(H, Wh)
    cudaStreamWaitEvent(s1, ev_fork, 0);
    cvt2_fp16_kernel<<<dim3(296, 2), 256, 0, s1>>>(hx, whh, dH, dWh, nA, nW);
    gemm_f16_kernel<<<grid, NTHREADS, SMEM_TOTAL, s1>>>(dH, dWh, dHG);
    cudaEventRecord(ev_join, s1);

    // join -> fuse
    cudaStreamWaitEvent(0, ev_join, 0);
    fuse_kernel<<<BATCH / 2, 256>>>(cx, ln_i_w, ln_i_b, ln_h_w, ln_h_b,
                                    ln_c_w, ln_c_b, out);
}